// round 9
// baseline (speedup 1.0000x reference)
#include <cuda_runtime.h>
#include <math.h>

#define BB 4
#define CC 64
#define NN 4096
#define KK 16
#define NSPL 2
#define ES 132   // edge stride: 128 edges (8 pts x 16 k) + 4 pad, float4-aligned

// ---------------- scratch (no allocations allowed) ----------------
__device__ float g_val_t[BB * NN * CC];   // y1 (value), layout (B,N,C)
__device__ float g_key_t[BB * NN * CC];   // key, layout (B,N,C)
__device__ float g_agg[BB * NN * CC];     // aggregated features, layout (B,N,C)
__device__ int   g_idx[BB * NN * KK];     // knn indices (final)
__device__ float g_knn_d[BB][NSPL][NN][KK];
__device__ int   g_knn_i[BB][NSPL][NN][KK];
__device__ float g_A1p[64 * 256];         // BN-folded A1, layout [c][a]

typedef unsigned long long ull;

__device__ __forceinline__ void fma4(float4& a, float w, const float4 v) {
    a.x = fmaf(w, v.x, a.x);
    a.y = fmaf(w, v.y, a.y);
    a.z = fmaf(w, v.z, a.z);
    a.w = fmaf(w, v.w, a.w);
}
// -------- packed f32x2 helpers (bitwise-identical IEEE fp32 lanes) --------
__device__ __forceinline__ ull bcast2(float v) {
    ull r; asm("mov.b64 %0, {%1, %1};" : "=l"(r) : "f"(v)); return r;
}
__device__ __forceinline__ void ffma2(ull& d, ull a, ull b) {
    asm("fma.rn.f32x2 %0, %1, %2, %0;" : "+l"(d) : "l"(a), "l"(b));
}
__device__ __forceinline__ void f4_to_p(const float4 v, ull& lo, ull& hi) {
    asm("mov.b64 %0, {%2, %3};\n\tmov.b64 %1, {%4, %5};"
        : "=l"(lo), "=l"(hi) : "f"(v.x), "f"(v.y), "f"(v.z), "f"(v.w));
}
__device__ __forceinline__ float4 p_to_f4(ull lo, ull hi) {
    float4 v;
    asm("mov.b64 {%0, %1}, %4;\n\tmov.b64 {%2, %3}, %5;"
        : "=f"(v.x), "=f"(v.y), "=f"(v.z), "=f"(v.w) : "l"(lo), "l"(hi));
    return v;
}

// ================= Kernel 0: fold BN2 into A1 -> g_A1p[c][a] =================
__global__ __launch_bounds__(256) void k_prep(
    const float* __restrict__ A1, const float* __restrict__ bn2_g,
    const float* __restrict__ bn2_v)
{
    int i = blockIdx.x * 256 + threadIdx.x;   // 64 blocks
    int c = i >> 8, a = i & 255;
    float s2 = bn2_g[a] * rsqrtf(bn2_v[a] + 1e-5f);
    g_A1p[i] = A1[a * 64 + c] * s2;
}

// ================= Kernel 1: y1 = W_start@y+b ; key = W_key@y1+b (transposed (B,N,C)) =================
__global__ __launch_bounds__(256) void k_linear_start_key(
    const float* __restrict__ y,
    const float* __restrict__ Ws_g, const float* __restrict__ bs_g,
    const float* __restrict__ Wk_g, const float* __restrict__ bk_g)
{
    __shared__ float ys[64][64];
    __shared__ float y1s[64][64];
    __shared__ float Ws[64][64];
    int b = blockIdx.y, n0 = blockIdx.x * 64, t = threadIdx.x;

#pragma unroll
    for (int i = 0; i < 16; i++) { int e = t + i * 256; Ws[e >> 6][e & 63] = Ws_g[e]; }
#pragma unroll
    for (int i = 0; i < 16; i++) {
        int e = t + i * 256; int c = e >> 6, p = e & 63;
        ys[c][p] = y[((size_t)b * CC + c) * NN + n0 + p];
    }
    __syncthreads();

    int p = t & 63, og = t >> 6;
    float acc[16];
#pragma unroll
    for (int i = 0; i < 16; i++) acc[i] = bs_g[og * 16 + i];
#pragma unroll 4
    for (int c = 0; c < 64; c++) {
        float yv = ys[c][p];
#pragma unroll
        for (int i = 0; i < 16; i++) acc[i] = fmaf(Ws[og * 16 + i][c], yv, acc[i]);
    }
#pragma unroll
    for (int i = 0; i < 16; i++) y1s[og * 16 + i][p] = acc[i];
    {
        float4* vo = (float4*)&g_val_t[(((size_t)b * NN) + n0 + p) * CC + og * 16];
        vo[0] = make_float4(acc[0], acc[1], acc[2], acc[3]);
        vo[1] = make_float4(acc[4], acc[5], acc[6], acc[7]);
        vo[2] = make_float4(acc[8], acc[9], acc[10], acc[11]);
        vo[3] = make_float4(acc[12], acc[13], acc[14], acc[15]);
    }
    __syncthreads();
#pragma unroll
    for (int i = 0; i < 16; i++) { int e = t + i * 256; Ws[e >> 6][e & 63] = Wk_g[e]; }
    __syncthreads();
#pragma unroll
    for (int i = 0; i < 16; i++) acc[i] = bk_g[og * 16 + i];
#pragma unroll 4
    for (int c = 0; c < 64; c++) {
        float yv = y1s[c][p];
#pragma unroll
        for (int i = 0; i < 16; i++) acc[i] = fmaf(Ws[og * 16 + i][c], yv, acc[i]);
    }
    {
        float4* ko = (float4*)&g_key_t[(((size_t)b * NN) + n0 + p) * CC + og * 16];
        ko[0] = make_float4(acc[0], acc[1], acc[2], acc[3]);
        ko[1] = make_float4(acc[4], acc[5], acc[6], acc[7]);
        ko[2] = make_float4(acc[8], acc[9], acc[10], acc[11]);
        ko[3] = make_float4(acc[12], acc[13], acc[14], acc[15]);
    }
}

// ================= Kernel 2a: KNN partial (candidate-split) =================
__global__ __launch_bounds__(64) void k_knn_part(const float* __restrict__ x)
{
    __shared__ float4 cand[64];
    int b = blockIdx.z, sp = blockIdx.y;
    int i = blockIdx.x * 64 + threadIdx.x;
    const float* xb = x + (size_t)b * 3 * NN;
    float qx = xb[i], qy = xb[NN + i], qz = xb[2 * NN + i];

    float bd[16]; int bi[16];
#pragma unroll
    for (int s = 0; s < 16; s++) { bd[s] = 3.0e38f; bi[s] = 0; }

    int base = sp * (NN / NSPL);
    for (int c0 = 0; c0 < NN / NSPL; c0 += 64) {
        int j = base + c0 + threadIdx.x;
        float ax = xb[j], ay = xb[NN + j], az = xb[2 * NN + j];
        cand[threadIdx.x] = make_float4(ax, ay, az, ax * ax + ay * ay + az * az);
        __syncthreads();
        for (int jj = 0; jj < 64; jj++) {
            float4 cv = cand[jj];
            float dot = qx * cv.x + qy * cv.y + qz * cv.z;
            float d = fmaf(-2.0f, dot, cv.w);
            if (d < bd[15]) {
                bd[15] = d; bi[15] = base + c0 + jj;
#pragma unroll
                for (int s = 15; s > 0; --s) {
                    if (bd[s] < bd[s - 1]) {
                        float td = bd[s]; bd[s] = bd[s - 1]; bd[s - 1] = td;
                        int ti = bi[s]; bi[s] = bi[s - 1]; bi[s - 1] = ti;
                    } else break;
                }
            }
        }
        __syncthreads();
    }
#pragma unroll
    for (int s = 0; s < 16; s++) { g_knn_d[b][sp][i][s] = bd[s]; g_knn_i[b][sp][i][s] = bi[s]; }
}

// ================= Kernel 2b: merge sorted partial lists =================
__global__ __launch_bounds__(128) void k_knn_merge()
{
    int g = blockIdx.x * 128 + threadIdx.x;
    int b = g >> 12, n = g & (NN - 1);
    float bd[16]; int bi[16];
#pragma unroll
    for (int s = 0; s < 16; s++) { bd[s] = g_knn_d[b][0][n][s]; bi[s] = g_knn_i[b][0][n][s]; }
    for (int s = 0; s < 16; s++) {
        float d = g_knn_d[b][1][n][s];
        if (d >= bd[15]) break;
        bd[15] = d; bi[15] = g_knn_i[b][1][n][s];
#pragma unroll
        for (int u = 15; u > 0; --u) {
            if (bd[u] < bd[u - 1]) {
                float td = bd[u]; bd[u] = bd[u - 1]; bd[u - 1] = td;
                int ti = bi[u]; bi[u] = bi[u - 1]; bi[u - 1] = ti;
            } else break;
        }
    }
#pragma unroll
    for (int s = 0; s < 16; s++) g_idx[((size_t)b * NN + n) * KK + s] = bi[s];
}

// ================= Kernel 3: fused attention, 8-point tiles, streamed A1 =================
struct __align__(16) S3 {
    float A2s[256][64];     // [h][c]
    float P2s[64][68];      // [h][c]
    float h1s[128][ES];     // one h-half of h1
    float th[64][ES];       // P1-hidden [h][e]
    float kgu[64][ES];      // key [c][e] -> u [c][e]
    float P1p[64][3];
    float Wq[64][3];
    float b1p[256];
    float s1s[64];
    float pb1p[64];
    float pb2s[64];
    float ab2s[64];
    float bqs[64];
    float posr[8][3][16];
    float qy[8][64];
    float vals[8][64];
};

#define NTILES (BB * NN / 8)   // 2048 tiles of 8 points

__global__ void __launch_bounds__(256, 1) k_attn(
    const float* __restrict__ x,
    const float* __restrict__ Wq_g, const float* __restrict__ bq_g,
    const float* __restrict__ P1, const float* __restrict__ pb1,
    const float* __restrict__ bn1_g, const float* __restrict__ bn1_b,
    const float* __restrict__ bn1_m, const float* __restrict__ bn1_v,
    const float* __restrict__ P2, const float* __restrict__ pb2,
    const float* __restrict__ A1, const float* __restrict__ ab1,
    const float* __restrict__ bn2_g, const float* __restrict__ bn2_b,
    const float* __restrict__ bn2_m, const float* __restrict__ bn2_v,
    const float* __restrict__ A2, const float* __restrict__ ab2)
{
    extern __shared__ char smraw[];
    S3& s = *(S3*)smraw;
    int t = threadIdx.x;

    // ---- fold BN biases, stage weights to smem (once per persistent block) ----
    {
        float s2 = bn2_g[t] * rsqrtf(bn2_v[t] + 1e-5f);
        s.b1p[t] = (ab1[t] - bn2_m[t]) * s2 + bn2_b[t];
    }
    if (t < 64) {
        float s1 = bn1_g[t] * rsqrtf(bn1_v[t] + 1e-5f);
        s.s1s[t] = s1;
        s.pb1p[t] = (pb1[t] - bn1_m[t]) * s1 + bn1_b[t];
        s.pb2s[t] = pb2[t];
        s.ab2s[t] = ab2[t];
        s.bqs[t] = bq_g[t];
    }
    if (t < 192) s.Wq[t / 3][t % 3] = Wq_g[t];
    __syncthreads();
    if (t < 192) s.P1p[t / 3][t % 3] = P1[t] * s.s1s[t / 3];
#pragma unroll
    for (int i = 0; i < 64; i++) {
        int e = t + i * 256; int c = e >> 8, h = e & 255;
        s.A2s[h][c] = A2[e];
    }
#pragma unroll
    for (int i = 0; i < 16; i++) {
        int e = t + i * 256; int c = e >> 6, h = e & 63;
        s.P2s[h][c] = P2[e];
    }
    __syncthreads();

    // thread identities
    const int cg = t >> 4, eg = t & 15;       // stages 2/5/epilogue: 4c x 8e
    const int c20 = cg * 4, e20 = eg * 8;
    const int ag = t >> 4, eg4 = t & 15;      // stage 4: 8a x 8e
    const int a0r = ag * 8, e40 = eg4 * 8;
    const int ptE = e20 >> 4;                 // epilogue point (0..7)
    const int half = eg & 1;

    for (int tile = blockIdx.x; tile < NTILES; tile += gridDim.x) {
        int b = tile >> 9;                    // 512 tiles per batch
        int n0 = (tile & 511) * 8;
        const float* xb = x + (size_t)b * 3 * NN;
        const int* idxb = &g_idx[(size_t)b * NN * KK];

        // ---- stage 0: key gather, posr, qy, vals ----
        {   // key gather: e = t&127 (edge), cq = t>>7 selects 32 c's
            int e = t & 127, cq = t >> 7;
            int pt = e >> 4, k = e & 15;
            int j = idxb[(n0 + pt) * KK + k];
            const float4* kp = (const float4*)&g_key_t[((size_t)b * NN + j) * CC + cq * 32];
#pragma unroll
            for (int q = 0; q < 8; q++) {
                float4 v = kp[q];
                int cb = cq * 32 + q * 4;
                s.kgu[cb + 0][e] = v.x; s.kgu[cb + 1][e] = v.y;
                s.kgu[cb + 2][e] = v.z; s.kgu[cb + 3][e] = v.w;
            }
        }
        if (t < 128) {
            int pt = t >> 4, k = t & 15;
            int j = idxb[(n0 + pt) * KK + k];
#pragma unroll
            for (int d = 0; d < 3; d++)
                s.posr[pt][d][k] = xb[d * NN + n0 + pt] - xb[d * NN + j];
        }
        {
            int c6 = t & 63;
#pragma unroll
            for (int ss = 0; ss < 2; ss++) {
                int pt = (t >> 6) + ss * 4;
                int n = n0 + pt;
                s.qy[pt][c6] = s.bqs[c6] + s.Wq[c6][0] * xb[n] + s.Wq[c6][1] * xb[NN + n]
                             + s.Wq[c6][2] * xb[2 * NN + n];
                s.vals[pt][c6] = g_val_t[((size_t)b * NN + n) * CC + c6];
            }
        }
        __syncthreads();   // sync0

        // ---- stage 1: th[h][e] = relu(P1'@pos_rel + pb1') ----
        {
            int h = t & 63, grp = t >> 6;     // grp covers 32 edges (2 points)
            float p0 = s.P1p[h][0], p1 = s.P1p[h][1], p2 = s.P1p[h][2], bb = s.pb1p[h];
#pragma unroll
            for (int g = 0; g < 8; g++) {
                int e0 = grp * 32 + g * 4;
                int pt = e0 >> 4;
                float4 o;
                float* ov = (float*)&o;
#pragma unroll
                for (int kk = 0; kk < 4; kk++) {
                    int k = (e0 + kk) & 15;
                    float a = bb + p0 * s.posr[pt][0][k] + p1 * s.posr[pt][1][k]
                                 + p2 * s.posr[pt][2][k];
                    ov[kk] = fmaxf(a, 0.0f);
                }
                *(float4*)&s.th[h][e0] = o;
            }
        }
        __syncthreads();   // sync1

        // ---- stage 2: pe = P2@th + pb2 (4c x 8e, FFMA2, kept in regs) ----
        ull PP[4][4];   // [ci][g0lo,g0hi,g1lo,g1hi]
        {
#pragma unroll
            for (int ci = 0; ci < 4; ci++) {
                ull bcc = bcast2(s.pb2s[c20 + ci]);
#pragma unroll
                for (int p = 0; p < 4; p++) PP[ci][p] = bcc;
            }
#pragma unroll 4
            for (int h = 0; h < 64; h++) {
                float4 w = *(const float4*)&s.P2s[h][c20];
                float4 tv0 = *(const float4*)&s.th[h][e20];
                float4 tv1 = *(const float4*)&s.th[h][e20 + 4];
                ull t0l, t0h, t1l, t1h;
                f4_to_p(tv0, t0l, t0h); f4_to_p(tv1, t1l, t1h);
                const float* wf = (const float*)&w;
#pragma unroll
                for (int ci = 0; ci < 4; ci++) {
                    ull wb = bcast2(wf[ci]);
                    ffma2(PP[ci][0], wb, t0l); ffma2(PP[ci][1], wb, t0h);
                    ffma2(PP[ci][2], wb, t1l); ffma2(PP[ci][3], wb, t1h);
                }
            }
        }
        // ---- stage 2b: u = (q - key) + pe (owner-thread cells, no barrier) ----
        float4 valv = *(const float4*)&s.vals[ptE][c20];
#pragma unroll
        for (int ci = 0; ci < 4; ci++) {
            float q = s.qy[ptE][c20 + ci];
            float4 pe0 = p_to_f4(PP[ci][0], PP[ci][1]);
            float4 pe1 = p_to_f4(PP[ci][2], PP[ci][3]);
            float4 k0 = *(const float4*)&s.kgu[c20 + ci][e20];
            float4 k1 = *(const float4*)&s.kgu[c20 + ci][e20 + 4];
            float4 u0, u1;
            u0.x = (q - k0.x) + pe0.x; u0.y = (q - k0.y) + pe0.y;
            u0.z = (q - k0.z) + pe0.z; u0.w = (q - k0.w) + pe0.w;
            u1.x = (q - k1.x) + pe1.x; u1.y = (q - k1.y) + pe1.y;
            u1.z = (q - k1.z) + pe1.z; u1.w = (q - k1.w) + pe1.w;
            *(float4*)&s.kgu[c20 + ci][e20] = u0;
            *(float4*)&s.kgu[c20 + ci][e20 + 4] = u1;
        }
        __syncthreads();   // sync2

        // ---- stages 4+5 over two h-halves ----
        ull LL[4][4];
#pragma unroll
        for (int ci = 0; ci < 4; ci++) {
            ull bcc = bcast2(s.ab2s[c20 + ci]);
#pragma unroll
            for (int p = 0; p < 4; p++) LL[ci][p] = bcc;
        }
#pragma unroll
        for (int r = 0; r < 2; r++) {
            // stage 4: h1[half] = relu(A1'@u + b1') — 8a x 8e, w streamed via LDG (depth-2 pipe)
            {
                const float4* wp = (const float4*)&g_A1p[r * 128 + a0r];  // row stride 256 floats
                ull AC[8][4];
#pragma unroll
                for (int ai = 0; ai < 8; ai++) {
                    ull bcc = bcast2(s.b1p[r * 128 + a0r + ai]);
#pragma unroll
                    for (int p = 0; p < 4; p++) AC[ai][p] = bcc;
                }
                float4 wA0 = __ldg(wp), wA1 = __ldg(wp + 1);
                float4 wB0 = __ldg(wp + 64), wB1 = __ldg(wp + 65);
#pragma unroll 2
                for (int c = 0; c < 64; c++) {
                    float4 w0 = wA0, w1 = wA1;
                    wA0 = wB0; wA1 = wB1;
                    if (c < 62) {
                        wB0 = __ldg(wp + (c + 2) * 64);
                        wB1 = __ldg(wp + (c + 2) * 64 + 1);
                    }
                    float4 u0 = *(const float4*)&s.kgu[c][e40];
                    float4 u1 = *(const float4*)&s.kgu[c][e40 + 4];
                    ull u0l, u0h, u1l, u1h;
                    f4_to_p(u0, u0l, u0h); f4_to_p(u1, u1l, u1h);
                    const float* wf0 = (const float*)&w0;
                    const float* wf1 = (const float*)&w1;
#pragma unroll
                    for (int ai = 0; ai < 4; ai++) {
                        ull wb = bcast2(wf0[ai]);
                        ffma2(AC[ai][0], wb, u0l); ffma2(AC[ai][1], wb, u0h);
                        ffma2(AC[ai][2], wb, u1l); ffma2(AC[ai][3], wb, u1h);
                    }
#pragma unroll
                    for (int ai = 0; ai < 4; ai++) {
                        ull wb = bcast2(wf1[ai]);
                        ffma2(AC[4 + ai][0], wb, u0l); ffma2(AC[4 + ai][1], wb, u0h);
                        ffma2(AC[4 + ai][2], wb, u1l); ffma2(AC[4 + ai][3], wb, u1h);
                    }
                }
#pragma unroll
                for (int ai = 0; ai < 8; ai++) {
                    float4 v0 = p_to_f4(AC[ai][0], AC[ai][1]);
                    float4 v1 = p_to_f4(AC[ai][2], AC[ai][3]);
                    v0.x = fmaxf(v0.x, 0.f); v0.y = fmaxf(v0.y, 0.f);
                    v0.z = fmaxf(v0.z, 0.f); v0.w = fmaxf(v0.w, 0.f);
                    v1.x = fmaxf(v1.x, 0.f); v1.y = fmaxf(v1.y, 0.f);
                    v1.z = fmaxf(v1.z, 0.f); v1.w = fmaxf(v1.w, 0.f);
                    *(float4*)&s.h1s[a0r + ai][e40] = v0;
                    *(float4*)&s.h1s[a0r + ai][e40 + 4] = v1;
                }
            }
            __syncthreads();
            // stage 5 partial: logits += A2[:, half]@h1[half]  (4c x 8e, FFMA2)
#pragma unroll 4
            for (int j = 0; j < 128; j++) {
                float4 w = *(const float4*)&s.A2s[r * 128 + j][c20];
                float4 h0 = *(const float4*)&s.h1s[j][e20];
                float4 h1 = *(const float4*)&s.h1s[j][e20 + 4];
                ull h0l, h0h, h1l, h1h;
                f4_to_p(h0, h0l, h0h); f4_to_p(h1, h1l, h1h);
                const float* wf = (const float*)&w;
#pragma unroll
                for (int ci = 0; ci < 4; ci++) {
                    ull wb = bcast2(wf[ci]);
                    ffma2(LL[ci][0], wb, h0l); ffma2(LL[ci][1], wb, h0h);
                    ffma2(LL[ci][2], wb, h1l); ffma2(LL[ci][3], wb, h1h);
                }
            }
            if (r == 0) __syncthreads();
        }

        // ---- epilogue: softmax over k (8k here + 8k in partner lane t^1) ----
        {
            float oa[4], os[4];
#pragma unroll
            for (int ci = 0; ci < 4; ci++) {
                float4 L0 = p_to_f4(LL[ci][0], LL[ci][1]);
                float4 L1 = p_to_f4(LL[ci][2], LL[ci][3]);
                float4 pe0 = p_to_f4(PP[ci][0], PP[ci][1]);
                float4 pe1 = p_to_f4(PP[ci][2], PP[ci][3]);
                float m = fmaxf(fmaxf(fmaxf(L0.x, L0.y), fmaxf(L0.z, L0.w)),
                                fmaxf(fmaxf(L1.x, L1.y), fmaxf(L1.z, L1.w)));
                m = fmaxf(m, __shfl_xor_sync(0xFFFFFFFFu, m, 1));
                float ex0 = __expf(L0.x - m), ex1 = __expf(L0.y - m);
                float ex2 = __expf(L0.z - m), ex3 = __expf(L0.w - m);
                float ex4 = __expf(L1.x - m), ex5 = __expf(L1.y - m);
                float ex6 = __expf(L1.z - m), ex7 = __expf(L1.w - m);
                float sv = ex0 + ex1 + ex2 + ex3 + ex4 + ex5 + ex6 + ex7;
                float av = ex0 * pe0.x + ex1 * pe0.y + ex2 * pe0.z + ex3 * pe0.w
                         + ex4 * pe1.x + ex5 * pe1.y + ex6 * pe1.z + ex7 * pe1.w;
                sv += __shfl_xor_sync(0xFFFFFFFFu, sv, 1);
                av += __shfl_xor_sync(0xFFFFFFFFu, av, 1);
                os[ci] = sv; oa[ci] = av;
            }
            if (half == 0) {
                float4 o = make_float4(valv.x + oa[0] / os[0], valv.y + oa[1] / os[1],
                                       valv.z + oa[2] / os[2], valv.w + oa[3] / os[3]);
                *(float4*)&g_agg[((size_t)b * NN + n0 + ptE) * CC + c20] = o;
            }
        }
        // no loop-end barrier: next-iter sync0..sync2 order all smem reuse
    }
}

// ================= Kernel 4: out = W_end @ agg + b_end + y =================
__global__ __launch_bounds__(256) void k_end(
    const float* __restrict__ y, const float* __restrict__ We_g,
    const float* __restrict__ be_g, float* __restrict__ out)
{
    __shared__ float As[64][65];
    __shared__ float Ws[64][64];
    int b = blockIdx.y, n0 = blockIdx.x * 64, t = threadIdx.x;
#pragma unroll
    for (int i = 0; i < 16; i++) { int e = t + i * 256; Ws[e >> 6][e & 63] = We_g[e]; }
#pragma unroll
    for (int i = 0; i < 16; i++) {
        int e = t + i * 256; int p = e >> 6, c = e & 63;
        As[p][c] = g_agg[((size_t)b * NN + n0 + p) * CC + c];
    }
    __syncthreads();
    int p = t & 63, og = t >> 6;
    float acc[16];
#pragma unroll
    for (int i = 0; i < 16; i++) acc[i] = be_g[og * 16 + i];
#pragma unroll 4
    for (int c = 0; c < 64; c++) {
        float av = As[p][c];
#pragma unroll
        for (int i = 0; i < 16; i++) acc[i] = fmaf(Ws[og * 16 + i][c], av, acc[i]);
    }
#pragma unroll
    for (int i = 0; i < 16; i++) {
        int o = og * 16 + i;
        size_t off = ((size_t)b * CC + o) * NN + n0 + p;
        out[off] = acc[i] + y[off];
    }
}

// ================= launcher =================
extern "C" void kernel_launch(void* const* d_in, const int* in_sizes, int n_in,
                              void* d_out, int out_size)
{
    const float* x       = (const float*)d_in[0];
    const float* y       = (const float*)d_in[1];
    const float* W_start = (const float*)d_in[2];
    const float* b_start = (const float*)d_in[3];
    const float* W_key   = (const float*)d_in[4];
    const float* b_key   = (const float*)d_in[5];
    const float* W_query = (const float*)d_in[6];
    const float* b_query = (const float*)d_in[7];
    const float* P1      = (const float*)d_in[8];
    const float* pb1     = (const float*)d_in[9];
    const float* bn1_g   = (const float*)d_in[10];
    const float* bn1_b   = (const float*)d_in[11];
    const float* bn1_m   = (const float*)d_in[12];
    const float* bn1_v   = (const float*)d_in[13];
    const float* P2      = (const float*)d_in[14];
    const float* pb2     = (const float*)d_in[15];
    const float* A1      = (const float*)d_in[16];
    const float* ab1     = (const float*)d_in[17];
    const float* bn2_g   = (const float*)d_in[18];
    const float* bn2_b   = (const float*)d_in[19];
    const float* bn2_m   = (const float*)d_in[20];
    const float* bn2_v   = (const float*)d_in[21];
    const float* A2      = (const float*)d_in[22];
    const float* ab2     = (const float*)d_in[23];
    const float* W_end   = (const float*)d_in[24];
    const float* b_end   = (const float*)d_in[25];

    cudaFuncSetAttribute(k_attn, cudaFuncAttributeMaxDynamicSharedMemorySize, (int)sizeof(S3));

    k_linear_start_key<<<dim3(NN / 64, BB), 256>>>(y, W_start, b_start, W_key, b_key);
    k_knn_part<<<dim3(NN / 64, NSPL, BB), 64>>>(x);
    k_knn_merge<<<BB * NN / 128, 128>>>();
    k_prep<<<64, 256>>>(A1, bn2_g, bn2_v);
    k_attn<<<148, 256, sizeof(S3)>>>(x, W_query, b_query,
                                     P1, pb1, bn1_g, bn1_b, bn1_m, bn1_v,
                                     P2, pb2, A1, ab1,
                                     bn2_g, bn2_b, bn2_m, bn2_v, A2, ab2);
    k_end<<<dim3(NN / 64, BB), 256>>>(y, W_end, b_end, (float*)d_out);
}

// round 10
// speedup vs baseline: 1.0005x; 1.0005x over previous
#include <cuda_runtime.h>
#include <math.h>

#define BB 4
#define CC 64
#define NN 4096
#define KK 16
#define NSPL 2
#define ES 132   // edge stride: 128 edges (8 pts x 16 k) + 4 pad, float4-aligned

// ---------------- scratch (no allocations allowed) ----------------
__device__ float g_val_t[BB * NN * CC];   // y1 (value), layout (B,N,C)
__device__ float g_key_t[BB * NN * CC];   // key, layout (B,N,C)
__device__ float g_agg[BB * NN * CC];     // aggregated features, layout (B,N,C)
__device__ int   g_idx[BB * NN * KK];     // knn indices (final)
__device__ float g_knn_d[BB][NSPL][NN][KK];
__device__ int   g_knn_i[BB][NSPL][NN][KK];
__device__ float g_A1p[64 * 256];         // BN-folded A1, layout [c][a]

typedef unsigned long long ull;

__device__ __forceinline__ void fma4(float4& a, float w, const float4 v) {
    a.x = fmaf(w, v.x, a.x);
    a.y = fmaf(w, v.y, a.y);
    a.z = fmaf(w, v.z, a.z);
    a.w = fmaf(w, v.w, a.w);
}
// -------- packed f32x2 helpers (bitwise-identical IEEE fp32 lanes) --------
__device__ __forceinline__ ull bcast2(float v) {
    ull r; asm("mov.b64 %0, {%1, %1};" : "=l"(r) : "f"(v)); return r;
}
__device__ __forceinline__ void ffma2(ull& d, ull a, ull b) {
    asm("fma.rn.f32x2 %0, %1, %2, %0;" : "+l"(d) : "l"(a), "l"(b));
}
__device__ __forceinline__ void f4_to_p(const float4 v, ull& lo, ull& hi) {
    asm("mov.b64 %0, {%2, %3};\n\tmov.b64 %1, {%4, %5};"
        : "=l"(lo), "=l"(hi) : "f"(v.x), "f"(v.y), "f"(v.z), "f"(v.w));
}
__device__ __forceinline__ float4 p_to_f4(ull lo, ull hi) {
    float4 v;
    asm("mov.b64 {%0, %1}, %4;\n\tmov.b64 {%2, %3}, %5;"
        : "=f"(v.x), "=f"(v.y), "=f"(v.z), "=f"(v.w) : "l"(lo), "l"(hi));
    return v;
}

// ================= Kernel 0: fold BN2 into A1 -> g_A1p[c][a] =================
__global__ __launch_bounds__(256) void k_prep(
    const float* __restrict__ A1, const float* __restrict__ bn2_g,
    const float* __restrict__ bn2_v)
{
    int i = blockIdx.x * 256 + threadIdx.x;   // 64 blocks
    int c = i >> 8, a = i & 255;
    float s2 = bn2_g[a] * rsqrtf(bn2_v[a] + 1e-5f);
    g_A1p[i] = A1[a * 64 + c] * s2;
}

// ================= Kernel 1: y1 = W_start@y+b ; key = W_key@y1+b (transposed (B,N,C)) =================
__global__ __launch_bounds__(256) void k_linear_start_key(
    const float* __restrict__ y,
    const float* __restrict__ Ws_g, const float* __restrict__ bs_g,
    const float* __restrict__ Wk_g, const float* __restrict__ bk_g)
{
    __shared__ float ys[64][64];
    __shared__ float y1s[64][64];
    __shared__ float Ws[64][64];
    int b = blockIdx.y, n0 = blockIdx.x * 64, t = threadIdx.x;

#pragma unroll
    for (int i = 0; i < 16; i++) { int e = t + i * 256; Ws[e >> 6][e & 63] = Ws_g[e]; }
#pragma unroll
    for (int i = 0; i < 16; i++) {
        int e = t + i * 256; int c = e >> 6, p = e & 63;
        ys[c][p] = y[((size_t)b * CC + c) * NN + n0 + p];
    }
    __syncthreads();

    int p = t & 63, og = t >> 6;
    float acc[16];
#pragma unroll
    for (int i = 0; i < 16; i++) acc[i] = bs_g[og * 16 + i];
#pragma unroll 4
    for (int c = 0; c < 64; c++) {
        float yv = ys[c][p];
#pragma unroll
        for (int i = 0; i < 16; i++) acc[i] = fmaf(Ws[og * 16 + i][c], yv, acc[i]);
    }
#pragma unroll
    for (int i = 0; i < 16; i++) y1s[og * 16 + i][p] = acc[i];
    {
        float4* vo = (float4*)&g_val_t[(((size_t)b * NN) + n0 + p) * CC + og * 16];
        vo[0] = make_float4(acc[0], acc[1], acc[2], acc[3]);
        vo[1] = make_float4(acc[4], acc[5], acc[6], acc[7]);
        vo[2] = make_float4(acc[8], acc[9], acc[10], acc[11]);
        vo[3] = make_float4(acc[12], acc[13], acc[14], acc[15]);
    }
    __syncthreads();
#pragma unroll
    for (int i = 0; i < 16; i++) { int e = t + i * 256; Ws[e >> 6][e & 63] = Wk_g[e]; }
    __syncthreads();
#pragma unroll
    for (int i = 0; i < 16; i++) acc[i] = bk_g[og * 16 + i];
#pragma unroll 4
    for (int c = 0; c < 64; c++) {
        float yv = y1s[c][p];
#pragma unroll
        for (int i = 0; i < 16; i++) acc[i] = fmaf(Ws[og * 16 + i][c], yv, acc[i]);
    }
    {
        float4* ko = (float4*)&g_key_t[(((size_t)b * NN) + n0 + p) * CC + og * 16];
        ko[0] = make_float4(acc[0], acc[1], acc[2], acc[3]);
        ko[1] = make_float4(acc[4], acc[5], acc[6], acc[7]);
        ko[2] = make_float4(acc[8], acc[9], acc[10], acc[11]);
        ko[3] = make_float4(acc[12], acc[13], acc[14], acc[15]);
    }
}

// ================= Kernel 2a: KNN partial (candidate-split) =================
__global__ __launch_bounds__(64) void k_knn_part(const float* __restrict__ x)
{
    __shared__ float4 cand[64];
    int b = blockIdx.z, sp = blockIdx.y;
    int i = blockIdx.x * 64 + threadIdx.x;
    const float* xb = x + (size_t)b * 3 * NN;
    float qx = xb[i], qy = xb[NN + i], qz = xb[2 * NN + i];

    float bd[16]; int bi[16];
#pragma unroll
    for (int s = 0; s < 16; s++) { bd[s] = 3.0e38f; bi[s] = 0; }

    int base = sp * (NN / NSPL);
    for (int c0 = 0; c0 < NN / NSPL; c0 += 64) {
        int j = base + c0 + threadIdx.x;
        float ax = xb[j], ay = xb[NN + j], az = xb[2 * NN + j];
        cand[threadIdx.x] = make_float4(ax, ay, az, ax * ax + ay * ay + az * az);
        __syncthreads();
        for (int jj = 0; jj < 64; jj++) {
            float4 cv = cand[jj];
            float dot = qx * cv.x + qy * cv.y + qz * cv.z;
            float d = fmaf(-2.0f, dot, cv.w);
            if (d < bd[15]) {
                bd[15] = d; bi[15] = base + c0 + jj;
#pragma unroll
                for (int s = 15; s > 0; --s) {
                    if (bd[s] < bd[s - 1]) {
                        float td = bd[s]; bd[s] = bd[s - 1]; bd[s - 1] = td;
                        int ti = bi[s]; bi[s] = bi[s - 1]; bi[s - 1] = ti;
                    } else break;
                }
            }
        }
        __syncthreads();
    }
#pragma unroll
    for (int s = 0; s < 16; s++) { g_knn_d[b][sp][i][s] = bd[s]; g_knn_i[b][sp][i][s] = bi[s]; }
}

// ================= Kernel 2b: merge sorted partial lists =================
__global__ __launch_bounds__(128) void k_knn_merge()
{
    int g = blockIdx.x * 128 + threadIdx.x;
    int b = g >> 12, n = g & (NN - 1);
    float bd[16]; int bi[16];
#pragma unroll
    for (int s = 0; s < 16; s++) { bd[s] = g_knn_d[b][0][n][s]; bi[s] = g_knn_i[b][0][n][s]; }
    for (int s = 0; s < 16; s++) {
        float d = g_knn_d[b][1][n][s];
        if (d >= bd[15]) break;
        bd[15] = d; bi[15] = g_knn_i[b][1][n][s];
#pragma unroll
        for (int u = 15; u > 0; --u) {
            if (bd[u] < bd[u - 1]) {
                float td = bd[u]; bd[u] = bd[u - 1]; bd[u - 1] = td;
                int ti = bi[u]; bi[u] = bi[u - 1]; bi[u - 1] = ti;
            } else break;
        }
    }
#pragma unroll
    for (int s = 0; s < 16; s++) g_idx[((size_t)b * NN + n) * KK + s] = bi[s];
}

// ================= Kernel 3: fused attention, 8-point tiles, streamed A1 =================
struct __align__(16) S3 {
    float A2s[256][64];     // [h][c]
    float P2s[64][68];      // [h][c]
    float h1s[128][ES];     // one h-half of h1
    float th[64][ES];       // P1-hidden [h][e]
    float kgu[64][ES];      // key [c][e] -> u [c][e]
    float P1p[64][3];
    float Wq[64][3];
    float b1p[256];
    float s1s[64];
    float pb1p[64];
    float pb2s[64];
    float ab2s[64];
    float bqs[64];
    float posr[8][3][16];
    float qy[8][64];
    float vals[8][64];
};

#define NTILES (BB * NN / 8)   // 2048 tiles of 8 points

__global__ void __launch_bounds__(256, 1) k_attn(
    const float* __restrict__ x,
    const float* __restrict__ Wq_g, const float* __restrict__ bq_g,
    const float* __restrict__ P1, const float* __restrict__ pb1,
    const float* __restrict__ bn1_g, const float* __restrict__ bn1_b,
    const float* __restrict__ bn1_m, const float* __restrict__ bn1_v,
    const float* __restrict__ P2, const float* __restrict__ pb2,
    const float* __restrict__ A1, const float* __restrict__ ab1,
    const float* __restrict__ bn2_g, const float* __restrict__ bn2_b,
    const float* __restrict__ bn2_m, const float* __restrict__ bn2_v,
    const float* __restrict__ A2, const float* __restrict__ ab2)
{
    extern __shared__ char smraw[];
    S3& s = *(S3*)smraw;
    int t = threadIdx.x;

    // ---- fold BN biases, stage weights to smem (once per persistent block) ----
    {
        float s2 = bn2_g[t] * rsqrtf(bn2_v[t] + 1e-5f);
        s.b1p[t] = (ab1[t] - bn2_m[t]) * s2 + bn2_b[t];
    }
    if (t < 64) {
        float s1 = bn1_g[t] * rsqrtf(bn1_v[t] + 1e-5f);
        s.s1s[t] = s1;
        s.pb1p[t] = (pb1[t] - bn1_m[t]) * s1 + bn1_b[t];
        s.pb2s[t] = pb2[t];
        s.ab2s[t] = ab2[t];
        s.bqs[t] = bq_g[t];
    }
    if (t < 192) s.Wq[t / 3][t % 3] = Wq_g[t];
    __syncthreads();
    if (t < 192) s.P1p[t / 3][t % 3] = P1[t] * s.s1s[t / 3];
#pragma unroll
    for (int i = 0; i < 64; i++) {
        int e = t + i * 256; int c = e >> 8, h = e & 255;
        s.A2s[h][c] = A2[e];
    }
#pragma unroll
    for (int i = 0; i < 16; i++) {
        int e = t + i * 256; int c = e >> 6, h = e & 63;
        s.P2s[h][c] = P2[e];
    }
    __syncthreads();

    // thread identities
    const int cg = t >> 4, eg = t & 15;       // stages 2/5/epilogue: 4c x 8e
    const int c20 = cg * 4, e20 = eg * 8;
    const int ag = t >> 4, eg4 = t & 15;      // stage 4: 8a x 8e
    const int a0r = ag * 8, e40 = eg4 * 8;
    const int ptE = e20 >> 4;                 // epilogue point (0..7)
    const int half = eg & 1;

    for (int tile = blockIdx.x; tile < NTILES; tile += gridDim.x) {
        int b = tile >> 9;                    // 512 tiles per batch
        int n0 = (tile & 511) * 8;
        const float* xb = x + (size_t)b * 3 * NN;
        const int* idxb = &g_idx[(size_t)b * NN * KK];

        // ---- stage 0: key gather, posr, qy, vals ----
        {   // key gather: e = t&127 (edge), cq = t>>7 selects 32 c's
            int e = t & 127, cq = t >> 7;
            int pt = e >> 4, k = e & 15;
            int j = idxb[(n0 + pt) * KK + k];
            const float4* kp = (const float4*)&g_key_t[((size_t)b * NN + j) * CC + cq * 32];
#pragma unroll
            for (int q = 0; q < 8; q++) {
                float4 v = kp[q];
                int cb = cq * 32 + q * 4;
                s.kgu[cb + 0][e] = v.x; s.kgu[cb + 1][e] = v.y;
                s.kgu[cb + 2][e] = v.z; s.kgu[cb + 3][e] = v.w;
            }
        }
        if (t < 128) {
            int pt = t >> 4, k = t & 15;
            int j = idxb[(n0 + pt) * KK + k];
#pragma unroll
            for (int d = 0; d < 3; d++)
                s.posr[pt][d][k] = xb[d * NN + n0 + pt] - xb[d * NN + j];
        }
        {
            int c6 = t & 63;
#pragma unroll
            for (int ss = 0; ss < 2; ss++) {
                int pt = (t >> 6) + ss * 4;
                int n = n0 + pt;
                s.qy[pt][c6] = s.bqs[c6] + s.Wq[c6][0] * xb[n] + s.Wq[c6][1] * xb[NN + n]
                             + s.Wq[c6][2] * xb[2 * NN + n];
                s.vals[pt][c6] = g_val_t[((size_t)b * NN + n) * CC + c6];
            }
        }
        __syncthreads();   // sync0

        // ---- stage 1: th[h][e] = relu(P1'@pos_rel + pb1') ----
        {
            int h = t & 63, grp = t >> 6;     // grp covers 32 edges (2 points)
            float p0 = s.P1p[h][0], p1 = s.P1p[h][1], p2 = s.P1p[h][2], bb = s.pb1p[h];
#pragma unroll
            for (int g = 0; g < 8; g++) {
                int e0 = grp * 32 + g * 4;
                int pt = e0 >> 4;
                float4 o;
                float* ov = (float*)&o;
#pragma unroll
                for (int kk = 0; kk < 4; kk++) {
                    int k = (e0 + kk) & 15;
                    float a = bb + p0 * s.posr[pt][0][k] + p1 * s.posr[pt][1][k]
                                 + p2 * s.posr[pt][2][k];
                    ov[kk] = fmaxf(a, 0.0f);
                }
                *(float4*)&s.th[h][e0] = o;
            }
        }
        __syncthreads();   // sync1

        // ---- stage 2: pe = P2@th + pb2 (4c x 8e, FFMA2, kept in regs) ----
        ull PP[4][4];   // [ci][g0lo,g0hi,g1lo,g1hi]
        {
#pragma unroll
            for (int ci = 0; ci < 4; ci++) {
                ull bcc = bcast2(s.pb2s[c20 + ci]);
#pragma unroll
                for (int p = 0; p < 4; p++) PP[ci][p] = bcc;
            }
#pragma unroll 4
            for (int h = 0; h < 64; h++) {
                float4 w = *(const float4*)&s.P2s[h][c20];
                float4 tv0 = *(const float4*)&s.th[h][e20];
                float4 tv1 = *(const float4*)&s.th[h][e20 + 4];
                ull t0l, t0h, t1l, t1h;
                f4_to_p(tv0, t0l, t0h); f4_to_p(tv1, t1l, t1h);
                const float* wf = (const float*)&w;
#pragma unroll
                for (int ci = 0; ci < 4; ci++) {
                    ull wb = bcast2(wf[ci]);
                    ffma2(PP[ci][0], wb, t0l); ffma2(PP[ci][1], wb, t0h);
                    ffma2(PP[ci][2], wb, t1l); ffma2(PP[ci][3], wb, t1h);
                }
            }
        }
        // ---- stage 2b: u = (q - key) + pe (owner-thread cells, no barrier) ----
        float4 valv = *(const float4*)&s.vals[ptE][c20];
#pragma unroll
        for (int ci = 0; ci < 4; ci++) {
            float q = s.qy[ptE][c20 + ci];
            float4 pe0 = p_to_f4(PP[ci][0], PP[ci][1]);
            float4 pe1 = p_to_f4(PP[ci][2], PP[ci][3]);
            float4 k0 = *(const float4*)&s.kgu[c20 + ci][e20];
            float4 k1 = *(const float4*)&s.kgu[c20 + ci][e20 + 4];
            float4 u0, u1;
            u0.x = (q - k0.x) + pe0.x; u0.y = (q - k0.y) + pe0.y;
            u0.z = (q - k0.z) + pe0.z; u0.w = (q - k0.w) + pe0.w;
            u1.x = (q - k1.x) + pe1.x; u1.y = (q - k1.y) + pe1.y;
            u1.z = (q - k1.z) + pe1.z; u1.w = (q - k1.w) + pe1.w;
            *(float4*)&s.kgu[c20 + ci][e20] = u0;
            *(float4*)&s.kgu[c20 + ci][e20 + 4] = u1;
        }
        __syncthreads();   // sync2

        // ---- stages 4+5 over two h-halves ----
        ull LL[4][4];
#pragma unroll
        for (int ci = 0; ci < 4; ci++) {
            ull bcc = bcast2(s.ab2s[c20 + ci]);
#pragma unroll
            for (int p = 0; p < 4; p++) LL[ci][p] = bcc;
        }
#pragma unroll
        for (int r = 0; r < 2; r++) {
            // stage 4: h1[half] = relu(A1'@u + b1') — 8a x 8e, w streamed via LDG (depth-2 pipe)
            {
                const float4* wp = (const float4*)&g_A1p[r * 128 + a0r];  // row stride 256 floats
                ull AC[8][4];
#pragma unroll
                for (int ai = 0; ai < 8; ai++) {
                    ull bcc = bcast2(s.b1p[r * 128 + a0r + ai]);
#pragma unroll
                    for (int p = 0; p < 4; p++) AC[ai][p] = bcc;
                }
                float4 wA0 = __ldg(wp), wA1 = __ldg(wp + 1);
                float4 wB0 = __ldg(wp + 64), wB1 = __ldg(wp + 65);
#pragma unroll 2
                for (int c = 0; c < 64; c++) {
                    float4 w0 = wA0, w1 = wA1;
                    wA0 = wB0; wA1 = wB1;
                    if (c < 62) {
                        wB0 = __ldg(wp + (c + 2) * 64);
                        wB1 = __ldg(wp + (c + 2) * 64 + 1);
                    }
                    float4 u0 = *(const float4*)&s.kgu[c][e40];
                    float4 u1 = *(const float4*)&s.kgu[c][e40 + 4];
                    ull u0l, u0h, u1l, u1h;
                    f4_to_p(u0, u0l, u0h); f4_to_p(u1, u1l, u1h);
                    const float* wf0 = (const float*)&w0;
                    const float* wf1 = (const float*)&w1;
#pragma unroll
                    for (int ai = 0; ai < 4; ai++) {
                        ull wb = bcast2(wf0[ai]);
                        ffma2(AC[ai][0], wb, u0l); ffma2(AC[ai][1], wb, u0h);
                        ffma2(AC[ai][2], wb, u1l); ffma2(AC[ai][3], wb, u1h);
                    }
#pragma unroll
                    for (int ai = 0; ai < 4; ai++) {
                        ull wb = bcast2(wf1[ai]);
                        ffma2(AC[4 + ai][0], wb, u0l); ffma2(AC[4 + ai][1], wb, u0h);
                        ffma2(AC[4 + ai][2], wb, u1l); ffma2(AC[4 + ai][3], wb, u1h);
                    }
                }
#pragma unroll
                for (int ai = 0; ai < 8; ai++) {
                    float4 v0 = p_to_f4(AC[ai][0], AC[ai][1]);
                    float4 v1 = p_to_f4(AC[ai][2], AC[ai][3]);
                    v0.x = fmaxf(v0.x, 0.f); v0.y = fmaxf(v0.y, 0.f);
                    v0.z = fmaxf(v0.z, 0.f); v0.w = fmaxf(v0.w, 0.f);
                    v1.x = fmaxf(v1.x, 0.f); v1.y = fmaxf(v1.y, 0.f);
                    v1.z = fmaxf(v1.z, 0.f); v1.w = fmaxf(v1.w, 0.f);
                    *(float4*)&s.h1s[a0r + ai][e40] = v0;
                    *(float4*)&s.h1s[a0r + ai][e40 + 4] = v1;
                }
            }
            __syncthreads();
            // stage 5 partial: logits += A2[:, half]@h1[half]  (4c x 8e, FFMA2)
#pragma unroll 4
            for (int j = 0; j < 128; j++) {
                float4 w = *(const float4*)&s.A2s[r * 128 + j][c20];
                float4 h0 = *(const float4*)&s.h1s[j][e20];
                float4 h1 = *(const float4*)&s.h1s[j][e20 + 4];
                ull h0l, h0h, h1l, h1h;
                f4_to_p(h0, h0l, h0h); f4_to_p(h1, h1l, h1h);
                const float* wf = (const float*)&w;
#pragma unroll
                for (int ci = 0; ci < 4; ci++) {
                    ull wb = bcast2(wf[ci]);
                    ffma2(LL[ci][0], wb, h0l); ffma2(LL[ci][1], wb, h0h);
                    ffma2(LL[ci][2], wb, h1l); ffma2(LL[ci][3], wb, h1h);
                }
            }
            if (r == 0) __syncthreads();
        }

        // ---- epilogue: softmax over k (8k here + 8k in partner lane t^1) ----
        {
            float oa[4], os[4];
#pragma unroll
            for (int ci = 0; ci < 4; ci++) {
                float4 L0 = p_to_f4(LL[ci][0], LL[ci][1]);
                float4 L1 = p_to_f4(LL[ci][2], LL[ci][3]);
                float4 pe0 = p_to_f4(PP[ci][0], PP[ci][1]);
                float4 pe1 = p_to_f4(PP[ci][2], PP[ci][3]);
                float m = fmaxf(fmaxf(fmaxf(L0.x, L0.y), fmaxf(L0.z, L0.w)),
                                fmaxf(fmaxf(L1.x, L1.y), fmaxf(L1.z, L1.w)));
                m = fmaxf(m, __shfl_xor_sync(0xFFFFFFFFu, m, 1));
                float ex0 = __expf(L0.x - m), ex1 = __expf(L0.y - m);
                float ex2 = __expf(L0.z - m), ex3 = __expf(L0.w - m);
                float ex4 = __expf(L1.x - m), ex5 = __expf(L1.y - m);
                float ex6 = __expf(L1.z - m), ex7 = __expf(L1.w - m);
                float sv = ex0 + ex1 + ex2 + ex3 + ex4 + ex5 + ex6 + ex7;
                float av = ex0 * pe0.x + ex1 * pe0.y + ex2 * pe0.z + ex3 * pe0.w
                         + ex4 * pe1.x + ex5 * pe1.y + ex6 * pe1.z + ex7 * pe1.w;
                sv += __shfl_xor_sync(0xFFFFFFFFu, sv, 1);
                av += __shfl_xor_sync(0xFFFFFFFFu, av, 1);
                os[ci] = sv; oa[ci] = av;
            }
            if (half == 0) {
                float4 o = make_float4(valv.x + oa[0] / os[0], valv.y + oa[1] / os[1],
                                       valv.z + oa[2] / os[2], valv.w + oa[3] / os[3]);
                *(float4*)&g_agg[((size_t)b * NN + n0 + ptE) * CC + c20] = o;
            }
        }
        // no loop-end barrier: next-iter sync0..sync2 order all smem reuse
    }
}

// ================= Kernel 4: out = W_end @ agg + b_end + y =================
__global__ __launch_bounds__(256) void k_end(
    const float* __restrict__ y, const float* __restrict__ We_g,
    const float* __restrict__ be_g, float* __restrict__ out)
{
    __shared__ float As[64][65];
    __shared__ float Ws[64][64];
    int b = blockIdx.y, n0 = blockIdx.x * 64, t = threadIdx.x;
#pragma unroll
    for (int i = 0; i < 16; i++) { int e = t + i * 256; Ws[e >> 6][e & 63] = We_g[e]; }
#pragma unroll
    for (int i = 0; i < 16; i++) {
        int e = t + i * 256; int p = e >> 6, c = e & 63;
        As[p][c] = g_agg[((size_t)b * NN + n0 + p) * CC + c];
    }
    __syncthreads();
    int p = t & 63, og = t >> 6;
    float acc[16];
#pragma unroll
    for (int i = 0; i < 16; i++) acc[i] = be_g[og * 16 + i];
#pragma unroll 4
    for (int c = 0; c < 64; c++) {
        float av = As[p][c];
#pragma unroll
        for (int i = 0; i < 16; i++) acc[i] = fmaf(Ws[og * 16 + i][c], av, acc[i]);
    }
#pragma unroll
    for (int i = 0; i < 16; i++) {
        int o = og * 16 + i;
        size_t off = ((size_t)b * CC + o) * NN + n0 + p;
        out[off] = acc[i] + y[off];
    }
}

// ================= launcher =================
extern "C" void kernel_launch(void* const* d_in, const int* in_sizes, int n_in,
                              void* d_out, int out_size)
{
    const float* x       = (const float*)d_in[0];
    const float* y       = (const float*)d_in[1];
    const float* W_start = (const float*)d_in[2];
    const float* b_start = (const float*)d_in[3];
    const float* W_key   = (const float*)d_in[4];
    const float* b_key   = (const float*)d_in[5];
    const float* W_query = (const float*)d_in[6];
    const float* b_query = (const float*)d_in[7];
    const float* P1      = (const float*)d_in[8];
    const float* pb1     = (const float*)d_in[9];
    const float* bn1_g   = (const float*)d_in[10];
    const float* bn1_b   = (const float*)d_in[11];
    const float* bn1_m   = (const float*)d_in[12];
    const float* bn1_v   = (const float*)d_in[13];
    const float* P2      = (const float*)d_in[14];
    const float* pb2     = (const float*)d_in[15];
    const float* A1      = (const float*)d_in[16];
    const float* ab1     = (const float*)d_in[17];
    const float* bn2_g   = (const float*)d_in[18];
    const float* bn2_b   = (const float*)d_in[19];
    const float* bn2_m   = (const float*)d_in[20];
    const float* bn2_v   = (const float*)d_in[21];
    const float* A2      = (const float*)d_in[22];
    const float* ab2     = (const float*)d_in[23];
    const float* W_end   = (const float*)d_in[24];
    const float* b_end   = (const float*)d_in[25];

    cudaFuncSetAttribute(k_attn, cudaFuncAttributeMaxDynamicSharedMemorySize, (int)sizeof(S3));

    k_linear_start_key<<<dim3(NN / 64, BB), 256>>>(y, W_start, b_start, W_key, b_key);
    k_knn_part<<<dim3(NN / 64, NSPL, BB), 64>>>(x);
    k_knn_merge<<<BB * NN / 128, 128>>>();
    k_prep<<<64, 256>>>(A1, bn2_g, bn2_v);
    k_attn<<<148, 256, sizeof(S3)>>>(x, W_query, b_query,
                                     P1, pb1, bn1_g, bn1_b, bn1_m, bn1_v,
                                     P2, pb2, A1, ab1,
                                     bn2_g, bn2_b, bn2_m, bn2_v, A2, ab2);
    k_end<<<dim3(NN / 64, BB), 256>>>(y, W_end, b_end, (float*)d_out);
}

// round 12
// speedup vs baseline: 1.5991x; 1.5983x over previous
#include <cuda_runtime.h>
#include <cuda_bf16.h>
#include <math.h>

#define BB 4
#define CC 64
#define NN 4096
#define KK 16
#define NSPL 2

__device__ float g_val_t[BB * NN * CC];
__device__ float g_key_t[BB * NN * CC];
__device__ float g_agg[BB * NN * CC];
__device__ int   g_idx[BB * NN * KK];
__device__ float g_knn_d[BB][NSPL][NN][KK];
__device__ int   g_knn_i[BB][NSPL][NN][KK];

typedef unsigned long long ull;
typedef unsigned int uint32;

// ---- smem byte offsets. H1 region (65536B) aliases U (16384) + th (33792) + spare. ----
#define OFF_H1   1024
#define OFF_U    1024          // bf16 [e=128][c=64], row 128B, swizzled
#define OFF_TH   17408         // f32 [h=64][e stride 132]
#define OFF_A1   66560         // bf16 [a=256][c=64], row 128B, swizzled    32768
#define OFF_A2   99328         // bf16 [c=64][h=256], row 512B, swizzled    32768
#define OFF_PES  132096        // f32 [e=128][c stride 68]                  34816
#define OFF_P2S  166912        // f32 [h=64][c stride 68]                   17408
#define OFF_P1P  184320
#define OFF_WQ   185088
#define OFF_B1P  185856
#define OFF_PB1P 186880
#define OFF_PB2S 187136
#define OFF_BQS  187392
#define OFF_S1S  187648
#define OFF_S2S  187904
#define OFF_POSR 188928        // f32 [8][3][16]
#define OFF_QY   190464        // f32 [8][64]
#define OFF_VALS 192512        // f32 [8][64]
#define SM_TOTAL 194560

#define CVTBF2(res, a, b) asm("cvt.rn.satfinite.bf16x2.f32 %0, %1, %2;" : "=r"(res) : "f"(b), "f"(a))

static __device__ __forceinline__ uint32 smem_u32(const void* p) {
    uint32 a;
    asm("{ .reg .u64 t; cvta.to.shared.u64 t, %1; cvt.u32.u64 %0, t; }" : "=r"(a) : "l"(p));
    return a;
}
static __device__ __forceinline__ void ldsm4(uint32& r0, uint32& r1, uint32& r2, uint32& r3, uint32 addr) {
    asm volatile("ldmatrix.sync.aligned.m8n8.x4.shared.b16 {%0,%1,%2,%3}, [%4];"
                 : "=r"(r0), "=r"(r1), "=r"(r2), "=r"(r3) : "r"(addr));
}
static __device__ __forceinline__ void mma16816(
    float& d0, float& d1, float& d2, float& d3,
    uint32 a0, uint32 a1, uint32 a2, uint32 a3, uint32 b0, uint32 b1)
{
    asm volatile(
        "mma.sync.aligned.m16n8k16.row.col.f32.bf16.bf16.f32 "
        "{%0,%1,%2,%3}, {%4,%5,%6,%7}, {%8,%9}, {%0,%1,%2,%3};"
        : "+f"(d0), "+f"(d1), "+f"(d2), "+f"(d3)
        : "r"(a0), "r"(a1), "r"(a2), "r"(a3), "r"(b0), "r"(b1));
}
static __device__ __forceinline__ ull bcast2(float v) {
    ull r; asm("mov.b64 %0, {%1, %1};" : "=l"(r) : "f"(v)); return r;
}
static __device__ __forceinline__ void ffma2(ull& d, ull a, ull b) {
    asm("fma.rn.f32x2 %0, %1, %2, %0;" : "+l"(d) : "l"(a), "l"(b));
}
static __device__ __forceinline__ void f4_to_p(const float4 v, ull& lo, ull& hi) {
    asm("mov.b64 %0, {%2, %3};\n\tmov.b64 %1, {%4, %5};"
        : "=l"(lo), "=l"(hi) : "f"(v.x), "f"(v.y), "f"(v.z), "f"(v.w));
}
static __device__ __forceinline__ float2 p_to_f2(ull v) {
    float2 f; asm("mov.b64 {%0, %1}, %2;" : "=f"(f.x), "=f"(f.y) : "l"(v)); return f;
}

// ================= Kernel 1: linear_start + key (transposed outputs) =================
__global__ __launch_bounds__(256) void k_linear_start_key(
    const float* __restrict__ y,
    const float* __restrict__ Ws_g, const float* __restrict__ bs_g,
    const float* __restrict__ Wk_g, const float* __restrict__ bk_g)
{
    __shared__ float ys[64][64];
    __shared__ float y1s[64][64];
    __shared__ float Ws[64][64];
    int b = blockIdx.y, n0 = blockIdx.x * 64, t = threadIdx.x;
#pragma unroll
    for (int i = 0; i < 16; i++) { int e = t + i * 256; Ws[e >> 6][e & 63] = Ws_g[e]; }
#pragma unroll
    for (int i = 0; i < 16; i++) {
        int e = t + i * 256; int c = e >> 6, p = e & 63;
        ys[c][p] = y[((size_t)b * CC + c) * NN + n0 + p];
    }
    __syncthreads();
    int p = t & 63, og = t >> 6;
    float acc[16];
#pragma unroll
    for (int i = 0; i < 16; i++) acc[i] = bs_g[og * 16 + i];
#pragma unroll 4
    for (int c = 0; c < 64; c++) {
        float yv = ys[c][p];
#pragma unroll
        for (int i = 0; i < 16; i++) acc[i] = fmaf(Ws[og * 16 + i][c], yv, acc[i]);
    }
#pragma unroll
    for (int i = 0; i < 16; i++) y1s[og * 16 + i][p] = acc[i];
    {
        float4* vo = (float4*)&g_val_t[(((size_t)b * NN) + n0 + p) * CC + og * 16];
        vo[0] = make_float4(acc[0], acc[1], acc[2], acc[3]);
        vo[1] = make_float4(acc[4], acc[5], acc[6], acc[7]);
        vo[2] = make_float4(acc[8], acc[9], acc[10], acc[11]);
        vo[3] = make_float4(acc[12], acc[13], acc[14], acc[15]);
    }
    __syncthreads();
#pragma unroll
    for (int i = 0; i < 16; i++) { int e = t + i * 256; Ws[e >> 6][e & 63] = Wk_g[e]; }
    __syncthreads();
#pragma unroll
    for (int i = 0; i < 16; i++) acc[i] = bk_g[og * 16 + i];
#pragma unroll 4
    for (int c = 0; c < 64; c++) {
        float yv = y1s[c][p];
#pragma unroll
        for (int i = 0; i < 16; i++) acc[i] = fmaf(Ws[og * 16 + i][c], yv, acc[i]);
    }
    {
        float4* ko = (float4*)&g_key_t[(((size_t)b * NN) + n0 + p) * CC + og * 16];
        ko[0] = make_float4(acc[0], acc[1], acc[2], acc[3]);
        ko[1] = make_float4(acc[4], acc[5], acc[6], acc[7]);
        ko[2] = make_float4(acc[8], acc[9], acc[10], acc[11]);
        ko[3] = make_float4(acc[12], acc[13], acc[14], acc[15]);
    }
}

// ================= Kernel 2a/2b: KNN =================
__global__ __launch_bounds__(64) void k_knn_part(const float* __restrict__ x)
{
    __shared__ float4 cand[64];
    int b = blockIdx.z, sp = blockIdx.y;
    int i = blockIdx.x * 64 + threadIdx.x;
    const float* xb = x + (size_t)b * 3 * NN;
    float qx = xb[i], qy = xb[NN + i], qz = xb[2 * NN + i];
    float bd[16]; int bi[16];
#pragma unroll
    for (int s = 0; s < 16; s++) { bd[s] = 3.0e38f; bi[s] = 0; }
    int base = sp * (NN / NSPL);
    for (int c0 = 0; c0 < NN / NSPL; c0 += 64) {
        int j = base + c0 + threadIdx.x;
        float ax = xb[j], ay = xb[NN + j], az = xb[2 * NN + j];
        cand[threadIdx.x] = make_float4(ax, ay, az, ax * ax + ay * ay + az * az);
        __syncthreads();
        for (int jj = 0; jj < 64; jj++) {
            float4 cv = cand[jj];
            float dot = qx * cv.x + qy * cv.y + qz * cv.z;
            float d = fmaf(-2.0f, dot, cv.w);
            if (d < bd[15]) {
                bd[15] = d; bi[15] = base + c0 + jj;
#pragma unroll
                for (int s = 15; s > 0; --s) {
                    if (bd[s] < bd[s - 1]) {
                        float td = bd[s]; bd[s] = bd[s - 1]; bd[s - 1] = td;
                        int ti = bi[s]; bi[s] = bi[s - 1]; bi[s - 1] = ti;
                    } else break;
                }
            }
        }
        __syncthreads();
    }
#pragma unroll
    for (int s = 0; s < 16; s++) { g_knn_d[b][sp][i][s] = bd[s]; g_knn_i[b][sp][i][s] = bi[s]; }
}

__global__ __launch_bounds__(128) void k_knn_merge()
{
    int g = blockIdx.x * 128 + threadIdx.x;
    int b = g >> 12, n = g & (NN - 1);
    float bd[16]; int bi[16];
#pragma unroll
    for (int s = 0; s < 16; s++) { bd[s] = g_knn_d[b][0][n][s]; bi[s] = g_knn_i[b][0][n][s]; }
    for (int s = 0; s < 16; s++) {
        float d = g_knn_d[b][1][n][s];
        if (d >= bd[15]) break;
        bd[15] = d; bi[15] = g_knn_i[b][1][n][s];
#pragma unroll
        for (int u = 15; u > 0; --u) {
            if (bd[u] < bd[u - 1]) {
                float td = bd[u]; bd[u] = bd[u - 1]; bd[u - 1] = td;
                int ti = bi[u]; bi[u] = bi[u - 1]; bi[u - 1] = ti;
            } else break;
        }
    }
#pragma unroll
    for (int s = 0; s < 16; s++) g_idx[((size_t)b * NN + n) * KK + s] = bi[s];
}

// ================= Kernel 3: mma.sync bf16 fused attention (8-pt tiles) =================
#define NTILES (BB * NN / 8)

__global__ void __launch_bounds__(256, 1) k_attn(
    const float* __restrict__ x,
    const float* __restrict__ Wq_g, const float* __restrict__ bq_g,
    const float* __restrict__ P1, const float* __restrict__ pb1,
    const float* __restrict__ bn1_g, const float* __restrict__ bn1_b,
    const float* __restrict__ bn1_m, const float* __restrict__ bn1_v,
    const float* __restrict__ P2, const float* __restrict__ pb2,
    const float* __restrict__ A1, const float* __restrict__ ab1,
    const float* __restrict__ bn2_g, const float* __restrict__ bn2_b,
    const float* __restrict__ bn2_m, const float* __restrict__ bn2_v,
    const float* __restrict__ A2, const float* __restrict__ ab2)
{
    extern __shared__ char sm[];
    const int t = threadIdx.x;
    const uint32 smb = smem_u32(sm);

    float* s_th   = (float*)(sm + OFF_TH);
    float* s_p2   = (float*)(sm + OFF_P2S);
    float* s_pes  = (float*)(sm + OFF_PES);
    float* s_p1p  = (float*)(sm + OFF_P1P);
    float* s_wq   = (float*)(sm + OFF_WQ);
    float* s_b1p  = (float*)(sm + OFF_B1P);
    float* s_pb1p = (float*)(sm + OFF_PB1P);
    float* s_pb2  = (float*)(sm + OFF_PB2S);
    float* s_bqs  = (float*)(sm + OFF_BQS);
    float* s_s1   = (float*)(sm + OFF_S1S);
    float* s_s2   = (float*)(sm + OFF_S2S);
    float* s_posr = (float*)(sm + OFF_POSR);
    float* s_qy   = (float*)(sm + OFF_QY);
    float* s_vals = (float*)(sm + OFF_VALS);

    // ---- prologue: fold BN, stage bf16 weights (once per persistent block) ----
    {
        float s2 = bn2_g[t] * rsqrtf(bn2_v[t] + 1e-5f);
        s_s2[t] = s2;
        s_b1p[t] = (ab1[t] - bn2_m[t]) * s2 + bn2_b[t];
    }
    if (t < 64) {
        float s1 = bn1_g[t] * rsqrtf(bn1_v[t] + 1e-5f);
        s_s1[t] = s1;
        s_pb1p[t] = (pb1[t] - bn1_m[t]) * s1 + bn1_b[t];
        s_pb2[t] = pb2[t];
        s_bqs[t] = bq_g[t];
    }
    if (t < 192) s_wq[t] = Wq_g[t];
    __syncthreads();
    if (t < 192) s_p1p[t] = P1[t] * s_s1[t / 3];
#pragma unroll
    for (int i = 0; i < 64; i++) {   // A1 bf16 [a][c], BN-folded, swizzled
        int idx = t + i * 256; int a = idx >> 6, c = idx & 63;
        *(__nv_bfloat16*)(sm + OFF_A1 + a * 128 + ((c * 2) ^ ((a & 7) << 4))) =
            __float2bfloat16(A1[idx] * s_s2[a]);
    }
#pragma unroll
    for (int i = 0; i < 64; i++) {   // A2 bf16 [c][h], swizzled (512B rows)
        int idx = t + i * 256; int c = idx >> 8, h = idx & 255;
        *(__nv_bfloat16*)(sm + OFF_A2 + c * 512 + ((h * 2) ^ ((c & 7) << 4))) =
            __float2bfloat16(A2[idx]);
    }
#pragma unroll
    for (int i = 0; i < 16; i++) {   // P2 f32 [h][c]
        int idx = t + i * 256; int h = idx >> 6, c = idx & 63;
        s_p2[h * 68 + c] = P2[c * 64 + h];
    }
    __syncthreads();

    // ---- thread identities ----
    const int lane = t & 31, w = t >> 5;
    const int g = lane >> 2, tig = lane & 3;
    const int e0 = w * 16;
    const int cg = t >> 4, eg = t & 15;
    const int c20 = cg * 4, e20 = eg * 8;
    // ldmatrix per-lane addressing constants
    const int ar = lane & 15;                      // A-frag row within 16
    const int acb = (lane >> 4) << 3;              // A-frag k-block (0/8)
    const int br = (lane & 7) + ((lane >> 4) << 3);// B-frag row within 16
    const int bkb = (lane & 8) ? 8 : 0;            // B-frag k-block
    const uint32 swsA = (uint32)((lane & 7) << 4); // row&7 swizzle (rows ≡ lane&7 mod 8)
    const uint32 aU_base  = smb + OFF_U  + (uint32)(e0 + ar) * 128;
    const uint32 aH_base  = smb + OFF_H1 + (uint32)(e0 + ar) * 512;
    const uint32 bA1_base = smb + OFF_A1 + (uint32)br * 128;
    const uint32 bA2_base = smb + OFF_A2 + (uint32)br * 512;

    for (int tile = blockIdx.x; tile < NTILES; tile += gridDim.x) {
        int b = tile >> 9;
        int n0 = (tile & 511) * 8;
        const float* xb = x + (size_t)b * 3 * NN;
        const int* idxb = &g_idx[(size_t)b * NN * KK];

        // ---- stage 0: key gather -> U bf16 (swizzled), posr, qy, vals ----
        {
            int e = t & 127, cq = t >> 7;
            int pt = e >> 4, k = e & 15;
            int j = idxb[(n0 + pt) * KK + k];
            const float4* kp = (const float4*)&g_key_t[((size_t)b * NN + j) * CC + cq * 32];
            uint32 rowb = (uint32)(e * 128), sw = (uint32)((e & 7) << 4);
#pragma unroll
            for (int q = 0; q < 8; q++) {
                float4 v = kp[q];
                uint2 r;
                CVTBF2(r.x, v.x, v.y);
                CVTBF2(r.y, v.z, v.w);
                uint32 c2 = (uint32)((cq * 32 + q * 4) * 2);
                *(uint2*)(sm + OFF_U + rowb + (c2 ^ sw)) = r;
            }
        }
        if (t < 128) {
            int pt = t >> 4, k = t & 15;
            int j = idxb[(n0 + pt) * KK + k];
#pragma unroll
            for (int d = 0; d < 3; d++)
                s_posr[(pt * 3 + d) * 16 + k] = xb[d * NN + n0 + pt] - xb[d * NN + j];
        }
        {
            int c6 = t & 63;
#pragma unroll
            for (int ss = 0; ss < 2; ss++) {
                int pt = (t >> 6) + ss * 4;
                int n = n0 + pt;
                s_qy[pt * 64 + c6] = s_bqs[c6] + s_wq[c6 * 3] * xb[n]
                    + s_wq[c6 * 3 + 1] * xb[NN + n] + s_wq[c6 * 3 + 2] * xb[2 * NN + n];
                s_vals[pt * 64 + c6] = g_val_t[((size_t)b * NN + n) * CC + c6];
            }
        }
        __syncthreads();

        // ---- stage 1: th[h][e] f32 = relu(P1'@posr + pb1') ----
        {
            int h = t & 63, grp = t >> 6;
            float p0 = s_p1p[h * 3], p1 = s_p1p[h * 3 + 1], p2 = s_p1p[h * 3 + 2], bb = s_pb1p[h];
#pragma unroll
            for (int gg = 0; gg < 8; gg++) {
                int ee0 = grp * 32 + gg * 4;
                const float* pr = &s_posr[(ee0 >> 4) * 48];
                float4 o;
                float* ov = (float*)&o;
#pragma unroll
                for (int kk = 0; kk < 4; kk++) {
                    int k = (ee0 + kk) & 15;
                    ov[kk] = fmaxf(bb + p0 * pr[k] + p1 * pr[16 + k] + p2 * pr[32 + k], 0.0f);
                }
                *(float4*)&s_th[h * 132 + ee0] = o;
            }
        }
        __syncthreads();

        // ---- stage 2: pe = P2@th + pb2 (fp32 FFMA2, 4c x 8e per thread) ----
        ull PP[4][4];
#pragma unroll
        for (int ci = 0; ci < 4; ci++) {
            ull bcc = bcast2(s_pb2[c20 + ci]);
#pragma unroll
            for (int p = 0; p < 4; p++) PP[ci][p] = bcc;
        }
#pragma unroll 4
        for (int h = 0; h < 64; h++) {
            float4 wv = *(const float4*)&s_p2[h * 68 + c20];
            float4 tv0 = *(const float4*)&s_th[h * 132 + e20];
            float4 tv1 = *(const float4*)&s_th[h * 132 + e20 + 4];
            ull t0, t1, t2, t3;
            f4_to_p(tv0, t0, t1); f4_to_p(tv1, t2, t3);
            const float* wf = (const float*)&wv;
#pragma unroll
            for (int ci = 0; ci < 4; ci++) {
                ull wb = bcast2(wf[ci]);
                ffma2(PP[ci][0], wb, t0); ffma2(PP[ci][1], wb, t1);
                ffma2(PP[ci][2], wb, t2); ffma2(PP[ci][3], wb, t3);
            }
        }
        float pef[4][8];
#pragma unroll
        for (int ci = 0; ci < 4; ci++)
#pragma unroll
            for (int p = 0; p < 4; p++) {
                float2 f = p_to_f2(PP[ci][p]);
                pef[ci][p * 2] = f.x; pef[ci][p * 2 + 1] = f.y;
            }
        // ---- stage 2b: u = (q - key) + pe -> U bf16 ; pes[e][c] f32 ----
        {
            int pt = e20 >> 4;
            float qv[4];
#pragma unroll
            for (int ci = 0; ci < 4; ci++) qv[ci] = s_qy[pt * 64 + c20 + ci];
#pragma unroll
            for (int ee = 0; ee < 8; ee++) {
                int e = e20 + ee;
                uint32 uoff = (uint32)(e * 128) + (((uint32)(c20 * 2)) ^ ((uint32)((e & 7) << 4)));
                uint2 kb = *(const uint2*)(sm + OFF_U + uoff);
                float k0 = __uint_as_float(kb.x << 16);
                float k1 = __uint_as_float(kb.x & 0xFFFF0000u);
                float k2 = __uint_as_float(kb.y << 16);
                float k3 = __uint_as_float(kb.y & 0xFFFF0000u);
                float u0 = (qv[0] - k0) + pef[0][ee];
                float u1 = (qv[1] - k1) + pef[1][ee];
                float u2 = (qv[2] - k2) + pef[2][ee];
                float u3 = (qv[3] - k3) + pef[3][ee];
                uint2 ur;
                CVTBF2(ur.x, u0, u1);
                CVTBF2(ur.y, u2, u3);
                *(uint2*)(sm + OFF_U + uoff) = ur;
                *(float4*)&s_pes[e * 68 + c20] =
                    make_float4(pef[0][ee], pef[1][ee], pef[2][ee], pef[3][ee]);
            }
        }
        __syncthreads();

        // ---- preload A-fragments of U (must complete before ANY H1 write: H1 aliases U) ----
        uint32 AU[4][4];
#pragma unroll
        for (int kk = 0; kk < 4; kk++)
            ldsm4(AU[kk][0], AU[kk][1], AU[kk][2], AU[kk][3],
                  aU_base + (((uint32)((kk * 16 + acb) * 2)) ^ swsA));
        __syncthreads();

        // ---- MMA1: D1[16e x 256a] = U @ A1^T; bias+relu -> H1 bf16 ----
#pragma unroll
        for (int chunk = 0; chunk < 4; chunk++) {
            float acc[8][4];
#pragma unroll
            for (int nt = 0; nt < 8; nt++)
#pragma unroll
                for (int q = 0; q < 4; q++) acc[nt][q] = 0.0f;
#pragma unroll
            for (int kk = 0; kk < 4; kk++) {
#pragma unroll
                for (int ntp = 0; ntp < 4; ntp++) {
                    uint32 b0, b1, b2, b3;
                    ldsm4(b0, b1, b2, b3,
                          bA1_base + (uint32)((chunk * 64 + ntp * 16) * 128)
                                   + (((uint32)((kk * 16 + bkb) * 2)) ^ swsA));
                    mma16816(acc[ntp * 2][0], acc[ntp * 2][1], acc[ntp * 2][2], acc[ntp * 2][3],
                             AU[kk][0], AU[kk][1], AU[kk][2], AU[kk][3], b0, b1);
                    mma16816(acc[ntp * 2 + 1][0], acc[ntp * 2 + 1][1], acc[ntp * 2 + 1][2], acc[ntp * 2 + 1][3],
                             AU[kk][0], AU[kk][1], AU[kk][2], AU[kk][3], b2, b3);
                }
            }
            // chunk epilogue: bias + relu + cvt -> H1[e][a]
            int row0 = e0 + g, row1 = e0 + 8 + g;
            uint32 swg = (uint32)(g << 4);
#pragma unroll
            for (int nt = 0; nt < 8; nt++) {
                int a0 = chunk * 64 + nt * 8 + 2 * tig;
                float b0v = s_b1p[a0], b1v = s_b1p[a0 + 1];
                float h00 = fmaxf(acc[nt][0] + b0v, 0.0f);
                float h01 = fmaxf(acc[nt][1] + b1v, 0.0f);
                float h10 = fmaxf(acc[nt][2] + b0v, 0.0f);
                float h11 = fmaxf(acc[nt][3] + b1v, 0.0f);
                uint32 p0, p1;
                CVTBF2(p0, h00, h01);
                CVTBF2(p1, h10, h11);
                uint32 co = ((uint32)(a0 * 2)) ^ swg;
                *(uint32*)(sm + OFF_H1 + row0 * 512 + co) = p0;
                *(uint32*)(sm + OFF_H1 + row1 * 512 + co) = p1;
            }
        }
        __syncthreads();

        // ---- MMA2: D2[16e x 64c] = H1 @ A2^T (K=256) ----
        float ac2[8][4];
#pragma unroll
        for (int nt = 0; nt < 8; nt++)
#pragma unroll
            for (int q = 0; q < 4; q++) ac2[nt][q] = 0.0f;
#pragma unroll 4
        for (int kk = 0; kk < 16; kk++) {
            uint32 A0, A1r, A2r, A3;
            ldsm4(A0, A1r, A2r, A3, aH_base + (((uint32)((kk * 16 + acb) * 2)) ^ swsA));
#pragma unroll
            for (int ntp = 0; ntp < 4; ntp++) {
                uint32 b0, b1, b2, b3;
                ldsm4(b0, b1, b2, b3,
                      bA2_base + (uint32)((ntp * 16) * 512)
                               + (((uint32)((kk * 16 + bkb) * 2)) ^ swsA));
                mma16816(ac2[ntp * 2][0], ac2[ntp * 2][1], ac2[ntp * 2][2], ac2[ntp * 2][3],
                         A0, A1r, A2r, A3, b0, b1);
                mma16816(ac2[ntp * 2 + 1][0], ac2[ntp * 2 + 1][1], ac2[ntp * 2 + 1][2], ac2[ntp * 2 + 1][3],
                         A0, A1r, A2r, A3, b2, b3);
            }
        }

        // ---- epilogue: softmax over the 16 e-rows (point = w) + aggregate ----
        {
            size_t orow = ((size_t)b * NN + n0 + w) * CC;
            int rA = (e0 + g) * 68, rB = (e0 + 8 + g) * 68;
#pragma unroll
            for (int nt = 0; nt < 8; nt++) {
                int c0 = nt * 8 + 2 * tig;
                float ex0 = __expf(ac2[nt][0]);   // logits tiny; ab2 cancels; no max needed
                float ex1 = __expf(ac2[nt][1]);
                float ex2 = __expf(ac2[nt][2]);
                float ex3 = __expf(ac2[nt][3]);
                float2 peA = *(const float2*)&s_pes[rA + c0];
                float2 peB = *(const float2*)&s_pes[rB + c0];
                float sv0 = ex0 + ex2, sv1 = ex1 + ex3;
                float tv0 = ex0 * peA.x + ex2 * peB.x;
                float tv1 = ex1 * peA.y + ex3 * peB.y;
                sv0 += __shfl_xor_sync(0xFFFFFFFFu, sv0, 4);
                sv1 += __shfl_xor_sync(0xFFFFFFFFu, sv1, 4);
                tv0 += __shfl_xor_sync(0xFFFFFFFFu, tv0, 4);
                tv1 += __shfl_xor_sync(0xFFFFFFFFu, tv1, 4);
                sv0 += __shfl_xor_sync(0xFFFFFFFFu, sv0, 8);
                sv1 += __shfl_xor_sync(0xFFFFFFFFu, sv1, 8);
                tv0 += __shfl_xor_sync(0xFFFFFFFFu, tv0, 8);
                tv1 += __shfl_xor_sync(0xFFFFFFFFu, tv1, 8);
                sv0 += __shfl_xor_sync(0xFFFFFFFFu, sv0, 16);
                sv1 += __shfl_xor_sync(0xFFFFFFFFu, sv1, 16);
                tv0 += __shfl_xor_sync(0xFFFFFFFFu, tv0, 16);
                tv1 += __shfl_xor_sync(0xFFFFFFFFu, tv1, 16);
                if (lane < 4) {
                    g_agg[orow + c0]     = s_vals[w * 64 + c0] + __fdividef(tv0, sv0);
                    g_agg[orow + c0 + 1] = s_vals[w * 64 + c0 + 1] + __fdividef(tv1, sv1);
                }
            }
        }
        __syncthreads();   // protect U/th(H1 alias)/pes/posr/qy/vals rewrite next tile
    }
}

// ================= Kernel 4: out = W_end @ agg + b_end + y =================
__global__ __launch_bounds__(256) void k_end(
    const float* __restrict__ y, const float* __restrict__ We_g,
    const float* __restrict__ be_g, float* __restrict__ out)
{
    __shared__ float As[64][65];
    __shared__ float Ws[64][64];
    int b = blockIdx.y, n0 = blockIdx.x * 64, t = threadIdx.x;
#pragma unroll
    for (int i = 0; i < 16; i++) { int e = t + i * 256; Ws[e >> 6][e & 63] = We_g[e]; }
#pragma unroll
    for (int i = 0; i < 16; i++) {
        int e = t + i * 256; int p = e >> 6, c = e & 63;
        As[p][c] = g_agg[((size_t)b * NN + n0 + p) * CC + c];
    }
    __syncthreads();
    int p = t & 63, og = t >> 6;
    float acc[16];
#pragma unroll
    for (int i = 0; i < 16; i++) acc[i] = be_g[og * 16 + i];
#pragma unroll 4
    for (int c = 0; c < 64; c++) {
        float av = As[p][c];
#pragma unroll
        for (int i = 0; i < 16; i++) acc[i] = fmaf(Ws[og * 16 + i][c], av, acc[i]);
    }
#pragma unroll
    for (int i = 0; i < 16; i++) {
        int o = og * 16 + i;
        size_t off = ((size_t)b * CC + o) * NN + n0 + p;
        out[off] = acc[i] + y[off];
    }
}

// ================= launcher =================
extern "C" void kernel_launch(void* const* d_in, const int* in_sizes, int n_in,
                              void* d_out, int out_size)
{
    const float* x       = (const float*)d_in[0];
    const float* y       = (const float*)d_in[1];
    const float* W_start = (const float*)d_in[2];
    const float* b_start = (const float*)d_in[3];
    const float* W_key   = (const float*)d_in[4];
    const float* b_key   = (const float*)d_in[5];
    const float* W_query = (const float*)d_in[6];
    const float* b_query = (const float*)d_in[7];
    const float* P1      = (const float*)d_in[8];
    const float* pb1     = (const float*)d_in[9];
    const float* bn1_g   = (const float*)d_in[10];
    const float* bn1_b   = (const float*)d_in[11];
    const float* bn1_m   = (const float*)d_in[12];
    const float* bn1_v   = (const float*)d_in[13];
    const float* P2      = (const float*)d_in[14];
    const float* pb2     = (const float*)d_in[15];
    const float* A1      = (const float*)d_in[16];
    const float* ab1     = (const float*)d_in[17];
    const float* bn2_g   = (const float*)d_in[18];
    const float* bn2_b   = (const float*)d_in[19];
    const float* bn2_m   = (const float*)d_in[20];
    const float* bn2_v   = (const float*)d_in[21];
    const float* A2      = (const float*)d_in[22];
    const float* ab2     = (const float*)d_in[23];
    const float* W_end   = (const float*)d_in[24];
    const float* b_end   = (const float*)d_in[25];

    cudaFuncSetAttribute(k_attn, cudaFuncAttributeMaxDynamicSharedMemorySize, SM_TOTAL);

    k_linear_start_key<<<dim3(NN / 64, BB), 256>>>(y, W_start, b_start, W_key, b_key);
    k_knn_part<<<dim3(NN / 64, NSPL, BB), 64>>>(x);
    k_knn_merge<<<BB * NN / 128, 128>>>();
    k_attn<<<148, 256, SM_TOTAL>>>(x, W_query, b_query,
                                   P1, pb1, bn1_g, bn1_b, bn1_m, bn1_v,
                                   P2, pb2, A1, ab1,
                                   bn2_g, bn2_b, bn2_m, bn2_v, A2, ab2);
    k_end<<<dim3(NN / 64, BB), 256>>>(y, W_end, b_end, (float*)d_out);
}

// round 13
// speedup vs baseline: 1.8150x; 1.1350x over previous
#include <cuda_runtime.h>
#include <cuda_bf16.h>
#include <math.h>

#define BB 4
#define CC 64
#define NN 4096
#define KK 16
#define NSPL 2

__device__ float g_val_t[BB * NN * CC];
__device__ float g_key_t[BB * NN * CC];
__device__ float g_agg[BB * NN * CC];
__device__ int   g_idx[BB * NN * KK];
__device__ float g_knn_d[BB][NSPL][NN][KK];
__device__ int   g_knn_i[BB][NSPL][NN][KK];

typedef unsigned long long ull;
typedef unsigned int uint32;

// ---- smem offsets. H1 (65536B) aliases U (16384) + THB (16384) + spare. ----
#define OFF_H1   1024
#define OFF_U    1024          // bf16 [e=128][c=64] rows 128B, swizzled
#define OFF_THB  17408         // bf16 [e=128][h=64] rows 128B, swizzled
#define OFF_A1   66560         // bf16 [a=256][c=64] rows 128B, swizzled   32768
#define OFF_A2   99328         // bf16 [c=64][h=256] rows 512B, swizzled   32768
#define OFF_P2B  132096        // bf16 [c=64][h=64] rows 128B, swizzled    8192
#define OFF_KEY  140288        // f32 [e=128][c stride 68]                 34816
#define OFF_P1P  175104
#define OFF_WQ   175872
#define OFF_B1P  176640
#define OFF_PB1P 177664
#define OFF_PB2S 177920
#define OFF_BQS  178176
#define OFF_S1S  178432
#define OFF_S2S  178688
#define OFF_POSR 179712        // f32 [8][3][16]
#define OFF_QY   181248        // f32 [8][64]
#define OFF_VALS 183296        // f32 [8][64]
#define SM_TOTAL 185344

#define CVTBF2(res, a, b) asm("cvt.rn.satfinite.bf16x2.f32 %0, %1, %2;" : "=r"(res) : "f"(b), "f"(a))

static __device__ __forceinline__ uint32 smem_u32(const void* p) {
    uint32 a;
    asm("{ .reg .u64 t; cvta.to.shared.u64 t, %1; cvt.u32.u64 %0, t; }" : "=r"(a) : "l"(p));
    return a;
}
static __device__ __forceinline__ void ldsm4(uint32& r0, uint32& r1, uint32& r2, uint32& r3, uint32 addr) {
    asm volatile("ldmatrix.sync.aligned.m8n8.x4.shared.b16 {%0,%1,%2,%3}, [%4];"
                 : "=r"(r0), "=r"(r1), "=r"(r2), "=r"(r3) : "r"(addr));
}
static __device__ __forceinline__ void mma16816(
    float& d0, float& d1, float& d2, float& d3,
    uint32 a0, uint32 a1, uint32 a2, uint32 a3, uint32 b0, uint32 b1)
{
    asm volatile(
        "mma.sync.aligned.m16n8k16.row.col.f32.bf16.bf16.f32 "
        "{%0,%1,%2,%3}, {%4,%5,%6,%7}, {%8,%9}, {%0,%1,%2,%3};"
        : "+f"(d0), "+f"(d1), "+f"(d2), "+f"(d3)
        : "r"(a0), "r"(a1), "r"(a2), "r"(a3), "r"(b0), "r"(b1));
}

// ================= Kernel 1: linear_start + key (transposed outputs) =================
__global__ __launch_bounds__(256) void k_linear_start_key(
    const float* __restrict__ y,
    const float* __restrict__ Ws_g, const float* __restrict__ bs_g,
    const float* __restrict__ Wk_g, const float* __restrict__ bk_g)
{
    __shared__ float ys[64][64];
    __shared__ float y1s[64][64];
    __shared__ float Ws[64][64];
    int b = blockIdx.y, n0 = blockIdx.x * 64, t = threadIdx.x;
#pragma unroll
    for (int i = 0; i < 16; i++) { int e = t + i * 256; Ws[e >> 6][e & 63] = Ws_g[e]; }
#pragma unroll
    for (int i = 0; i < 16; i++) {
        int e = t + i * 256; int c = e >> 6, p = e & 63;
        ys[c][p] = y[((size_t)b * CC + c) * NN + n0 + p];
    }
    __syncthreads();
    int p = t & 63, og = t >> 6;
    float acc[16];
#pragma unroll
    for (int i = 0; i < 16; i++) acc[i] = bs_g[og * 16 + i];
#pragma unroll 4
    for (int c = 0; c < 64; c++) {
        float yv = ys[c][p];
#pragma unroll
        for (int i = 0; i < 16; i++) acc[i] = fmaf(Ws[og * 16 + i][c], yv, acc[i]);
    }
#pragma unroll
    for (int i = 0; i < 16; i++) y1s[og * 16 + i][p] = acc[i];
    {
        float4* vo = (float4*)&g_val_t[(((size_t)b * NN) + n0 + p) * CC + og * 16];
        vo[0] = make_float4(acc[0], acc[1], acc[2], acc[3]);
        vo[1] = make_float4(acc[4], acc[5], acc[6], acc[7]);
        vo[2] = make_float4(acc[8], acc[9], acc[10], acc[11]);
        vo[3] = make_float4(acc[12], acc[13], acc[14], acc[15]);
    }
    __syncthreads();
#pragma unroll
    for (int i = 0; i < 16; i++) { int e = t + i * 256; Ws[e >> 6][e & 63] = Wk_g[e]; }
    __syncthreads();
#pragma unroll
    for (int i = 0; i < 16; i++) acc[i] = bk_g[og * 16 + i];
#pragma unroll 4
    for (int c = 0; c < 64; c++) {
        float yv = y1s[c][p];
#pragma unroll
        for (int i = 0; i < 16; i++) acc[i] = fmaf(Ws[og * 16 + i][c], yv, acc[i]);
    }
    {
        float4* ko = (float4*)&g_key_t[(((size_t)b * NN) + n0 + p) * CC + og * 16];
        ko[0] = make_float4(acc[0], acc[1], acc[2], acc[3]);
        ko[1] = make_float4(acc[4], acc[5], acc[6], acc[7]);
        ko[2] = make_float4(acc[8], acc[9], acc[10], acc[11]);
        ko[3] = make_float4(acc[12], acc[13], acc[14], acc[15]);
    }
}

// ================= Kernel 2a/2b: KNN =================
__global__ __launch_bounds__(64) void k_knn_part(const float* __restrict__ x)
{
    __shared__ float4 cand[64];
    int b = blockIdx.z, sp = blockIdx.y;
    int i = blockIdx.x * 64 + threadIdx.x;
    const float* xb = x + (size_t)b * 3 * NN;
    float qx = xb[i], qy = xb[NN + i], qz = xb[2 * NN + i];
    float bd[16]; int bi[16];
#pragma unroll
    for (int s = 0; s < 16; s++) { bd[s] = 3.0e38f; bi[s] = 0; }
    int base = sp * (NN / NSPL);
    for (int c0 = 0; c0 < NN / NSPL; c0 += 64) {
        int j = base + c0 + threadIdx.x;
        float ax = xb[j], ay = xb[NN + j], az = xb[2 * NN + j];
        cand[threadIdx.x] = make_float4(ax, ay, az, ax * ax + ay * ay + az * az);
        __syncthreads();
        for (int jj = 0; jj < 64; jj++) {
            float4 cv = cand[jj];
            float dot = qx * cv.x + qy * cv.y + qz * cv.z;
            float d = fmaf(-2.0f, dot, cv.w);
            if (d < bd[15]) {
                bd[15] = d; bi[15] = base + c0 + jj;
#pragma unroll
                for (int s = 15; s > 0; --s) {
                    if (bd[s] < bd[s - 1]) {
                        float td = bd[s]; bd[s] = bd[s - 1]; bd[s - 1] = td;
                        int ti = bi[s]; bi[s] = bi[s - 1]; bi[s - 1] = ti;
                    } else break;
                }
            }
        }
        __syncthreads();
    }
#pragma unroll
    for (int s = 0; s < 16; s++) { g_knn_d[b][sp][i][s] = bd[s]; g_knn_i[b][sp][i][s] = bi[s]; }
}

__global__ __launch_bounds__(128) void k_knn_merge()
{
    int g = blockIdx.x * 128 + threadIdx.x;
    int b = g >> 12, n = g & (NN - 1);
    float bd[16]; int bi[16];
#pragma unroll
    for (int s = 0; s < 16; s++) { bd[s] = g_knn_d[b][0][n][s]; bi[s] = g_knn_i[b][0][n][s]; }
    for (int s = 0; s < 16; s++) {
        float d = g_knn_d[b][1][n][s];
        if (d >= bd[15]) break;
        bd[15] = d; bi[15] = g_knn_i[b][1][n][s];
#pragma unroll
        for (int u = 15; u > 0; --u) {
            if (bd[u] < bd[u - 1]) {
                float td = bd[u]; bd[u] = bd[u - 1]; bd[u - 1] = td;
                int ti = bi[u]; bi[u] = bi[u - 1]; bi[u - 1] = ti;
            } else break;
        }
    }
#pragma unroll
    for (int s = 0; s < 16; s++) g_idx[((size_t)b * NN + n) * KK + s] = bi[s];
}

// ================= Kernel 3: full-mma fused attention (8-pt tiles) =================
#define NTILES (BB * NN / 8)

__global__ void __launch_bounds__(256, 1) k_attn(
    const float* __restrict__ x,
    const float* __restrict__ Wq_g, const float* __restrict__ bq_g,
    const float* __restrict__ P1, const float* __restrict__ pb1,
    const float* __restrict__ bn1_g, const float* __restrict__ bn1_b,
    const float* __restrict__ bn1_m, const float* __restrict__ bn1_v,
    const float* __restrict__ P2, const float* __restrict__ pb2,
    const float* __restrict__ A1, const float* __restrict__ ab1,
    const float* __restrict__ bn2_g, const float* __restrict__ bn2_b,
    const float* __restrict__ bn2_m, const float* __restrict__ bn2_v,
    const float* __restrict__ A2, const float* __restrict__ ab2)
{
    extern __shared__ char sm[];
    const int t = threadIdx.x;
    const uint32 smb = smem_u32(sm);

    float* s_key  = (float*)(sm + OFF_KEY);
    float* s_p1p  = (float*)(sm + OFF_P1P);
    float* s_wq   = (float*)(sm + OFF_WQ);
    float* s_b1p  = (float*)(sm + OFF_B1P);
    float* s_pb1p = (float*)(sm + OFF_PB1P);
    float* s_pb2  = (float*)(sm + OFF_PB2S);
    float* s_bqs  = (float*)(sm + OFF_BQS);
    float* s_s1   = (float*)(sm + OFF_S1S);
    float* s_s2   = (float*)(sm + OFF_S2S);
    float* s_posr = (float*)(sm + OFF_POSR);
    float* s_qy   = (float*)(sm + OFF_QY);
    float* s_vals = (float*)(sm + OFF_VALS);

    // ---- prologue: fold BN, stage bf16 weights ----
    {
        float s2 = bn2_g[t] * rsqrtf(bn2_v[t] + 1e-5f);
        s_s2[t] = s2;
        s_b1p[t] = (ab1[t] - bn2_m[t]) * s2 + bn2_b[t];
    }
    if (t < 64) {
        float s1 = bn1_g[t] * rsqrtf(bn1_v[t] + 1e-5f);
        s_s1[t] = s1;
        s_pb1p[t] = (pb1[t] - bn1_m[t]) * s1 + bn1_b[t];
        s_pb2[t] = pb2[t];
        s_bqs[t] = bq_g[t];
    }
    if (t < 192) s_wq[t] = Wq_g[t];
    __syncthreads();
    if (t < 192) s_p1p[t] = P1[t] * s_s1[t / 3];
#pragma unroll
    for (int i = 0; i < 64; i++) {   // A1 bf16 [a][c]
        int idx = t + i * 256; int a = idx >> 6, c = idx & 63;
        *(__nv_bfloat16*)(sm + OFF_A1 + a * 128 + ((c * 2) ^ ((a & 7) << 4))) =
            __float2bfloat16(A1[idx] * s_s2[a]);
    }
#pragma unroll
    for (int i = 0; i < 64; i++) {   // A2 bf16 [c][h]
        int idx = t + i * 256; int c = idx >> 8, h = idx & 255;
        *(__nv_bfloat16*)(sm + OFF_A2 + c * 512 + ((h * 2) ^ ((c & 7) << 4))) =
            __float2bfloat16(A2[idx]);
    }
#pragma unroll
    for (int i = 0; i < 16; i++) {   // P2 bf16 [c][h]
        int idx = t + i * 256; int c = idx >> 6, h = idx & 63;
        *(__nv_bfloat16*)(sm + OFF_P2B + c * 128 + ((h * 2) ^ ((c & 7) << 4))) =
            __float2bfloat16(P2[idx]);
    }
    __syncthreads();

    // ---- thread identities ----
    const int lane = t & 31, w = t >> 5;
    const int g = lane >> 2, tig = lane & 3;
    const int e0 = w * 16;
    const int ar = lane & 15;                       // A-frag row in 16
    const int acb = (lane >> 4) << 3;               // A-frag k-block
    const int br = (lane & 7) + ((lane >> 4) << 3); // B-frag row in 16
    const int bkb = (lane & 8) ? 8 : 0;             // B-frag k-block
    const uint32 swsA = (uint32)((lane & 7) << 4);
    const uint32 aU_base  = smb + OFF_U   + (uint32)(e0 + ar) * 128;
    const uint32 aTH_base = smb + OFF_THB + (uint32)(e0 + ar) * 128;
    const uint32 aH_base  = smb + OFF_H1  + (uint32)(e0 + ar) * 512;
    const uint32 bA1_base = smb + OFF_A1  + (uint32)br * 128;
    const uint32 bA2_base = smb + OFF_A2  + (uint32)br * 512;
    const uint32 bP2_base = smb + OFF_P2B + (uint32)br * 128;

    for (int tile = blockIdx.x; tile < NTILES; tile += gridDim.x) {
        int b = tile >> 9;
        int n0 = (tile & 511) * 8;
        const float* xb = x + (size_t)b * 3 * NN;
        const int* idxb = &g_idx[(size_t)b * NN * KK];

        // ---- stage 0: key gather (f32), posr, qy, vals ----
        {
            int e = t & 127, cq = t >> 7;
            int pt = e >> 4, k = e & 15;
            int j = idxb[(n0 + pt) * KK + k];
            const float4* kp = (const float4*)&g_key_t[((size_t)b * NN + j) * CC + cq * 32];
            float* kd = &s_key[e * 68 + cq * 32];
#pragma unroll
            for (int q = 0; q < 8; q++) *(float4*)&kd[q * 4] = kp[q];
        }
        if (t < 128) {
            int pt = t >> 4, k = t & 15;
            int j = idxb[(n0 + pt) * KK + k];
#pragma unroll
            for (int d = 0; d < 3; d++)
                s_posr[(pt * 3 + d) * 16 + k] = xb[d * NN + n0 + pt] - xb[d * NN + j];
        }
        {
            int c6 = t & 63;
#pragma unroll
            for (int ss = 0; ss < 2; ss++) {
                int pt = (t >> 6) + ss * 4;
                int n = n0 + pt;
                s_qy[pt * 64 + c6] = s_bqs[c6] + s_wq[c6 * 3] * xb[n]
                    + s_wq[c6 * 3 + 1] * xb[NN + n] + s_wq[c6 * 3 + 2] * xb[2 * NN + n];
                s_vals[pt * 64 + c6] = g_val_t[((size_t)b * NN + n) * CC + c6];
            }
        }
        __syncthreads();   // b0

        // ---- stage 1: th bf16 [e][h] (warp-private rows: e = t>>1 in [16w,16w+16)) ----
        {
            int e = t >> 1, h0 = (t & 1) * 32;
            int pt = e >> 4, k = e & 15;
            const float* pr = &s_posr[pt * 48];
            float px = pr[k], py = pr[16 + k], pz = pr[32 + k];
            uint32 sw = (uint32)((e & 7) << 4);
#pragma unroll
            for (int q = 0; q < 4; q++) {
                uint32 pk[4];
#pragma unroll
                for (int ii = 0; ii < 4; ii++) {
                    int h = h0 + q * 8 + ii * 2;
                    float f0 = fmaxf(s_pb1p[h] + s_p1p[h * 3] * px
                            + s_p1p[h * 3 + 1] * py + s_p1p[h * 3 + 2] * pz, 0.0f);
                    float f1 = fmaxf(s_pb1p[h + 1] + s_p1p[h * 3 + 3] * px
                            + s_p1p[h * 3 + 4] * py + s_p1p[h * 3 + 5] * pz, 0.0f);
                    CVTBF2(pk[ii], f0, f1);
                }
                *(uint4*)(sm + OFF_THB + e * 128 + (((uint32)((h0 + q * 8) * 2)) ^ sw)) = *(uint4*)pk;
            }
        }
        __syncwarp();

        // ---- MMA_pe: PE[16e x 64c] = th @ P2^T (K=64); + pb2 ----
        float PE[8][4];
#pragma unroll
        for (int nt = 0; nt < 8; nt++)
#pragma unroll
            for (int q = 0; q < 4; q++) PE[nt][q] = 0.0f;
#pragma unroll
        for (int kk = 0; kk < 4; kk++) {
            uint32 A0, A1r, A2r, A3;
            ldsm4(A0, A1r, A2r, A3, aTH_base + (((uint32)((kk * 16 + acb) * 2)) ^ swsA));
#pragma unroll
            for (int ntp = 0; ntp < 4; ntp++) {
                uint32 b0, b1, b2, b3;
                ldsm4(b0, b1, b2, b3,
                      bP2_base + (uint32)((ntp * 16) * 128)
                               + (((uint32)((kk * 16 + bkb) * 2)) ^ swsA));
                mma16816(PE[ntp * 2][0], PE[ntp * 2][1], PE[ntp * 2][2], PE[ntp * 2][3],
                         A0, A1r, A2r, A3, b0, b1);
                mma16816(PE[ntp * 2 + 1][0], PE[ntp * 2 + 1][1], PE[ntp * 2 + 1][2], PE[ntp * 2 + 1][3],
                         A0, A1r, A2r, A3, b2, b3);
            }
        }
        // ---- u = (q - key) + pe (frag-wise) -> U bf16 ----
        {
            int row0 = e0 + g, row1 = e0 + 8 + g;
#pragma unroll
            for (int nt = 0; nt < 8; nt++) {
                int c0 = nt * 8 + 2 * tig;
                float pb0 = s_pb2[c0], pb1v = s_pb2[c0 + 1];
                PE[nt][0] += pb0; PE[nt][1] += pb1v;
                PE[nt][2] += pb0; PE[nt][3] += pb1v;
                float2 qv = *(const float2*)&s_qy[w * 64 + c0];
                float2 kA = *(const float2*)&s_key[row0 * 68 + c0];
                float2 kB = *(const float2*)&s_key[row1 * 68 + c0];
                float u00 = (qv.x - kA.x) + PE[nt][0];
                float u01 = (qv.y - kA.y) + PE[nt][1];
                float u10 = (qv.x - kB.x) + PE[nt][2];
                float u11 = (qv.y - kB.y) + PE[nt][3];
                uint32 p0, p1;
                CVTBF2(p0, u00, u01);
                CVTBF2(p1, u10, u11);
                uint32 co = ((uint32)(c0 * 2)) ^ ((uint32)(g << 4));
                *(uint32*)(sm + OFF_U + row0 * 128 + co) = p0;
                *(uint32*)(sm + OFF_U + row1 * 128 + co) = p1;
            }
        }
        __syncwarp();

        // ---- preload A-frags of U (before H1 writes overwrite the alias region) ----
        uint32 AU[4][4];
#pragma unroll
        for (int kk = 0; kk < 4; kk++)
            ldsm4(AU[kk][0], AU[kk][1], AU[kk][2], AU[kk][3],
                  aU_base + (((uint32)((kk * 16 + acb) * 2)) ^ swsA));
        __syncthreads();   // b1: all U/th reads done before H1 writes

        // ---- MMA1: D1[16e x 256a] = U @ A1^T; bias+relu -> H1 bf16 ----
#pragma unroll
        for (int chunk = 0; chunk < 4; chunk++) {
            float acc[8][4];
#pragma unroll
            for (int nt = 0; nt < 8; nt++)
#pragma unroll
                for (int q = 0; q < 4; q++) acc[nt][q] = 0.0f;
#pragma unroll
            for (int kk = 0; kk < 4; kk++) {
#pragma unroll
                for (int ntp = 0; ntp < 4; ntp++) {
                    uint32 b0, b1, b2, b3;
                    ldsm4(b0, b1, b2, b3,
                          bA1_base + (uint32)((chunk * 64 + ntp * 16) * 128)
                                   + (((uint32)((kk * 16 + bkb) * 2)) ^ swsA));
                    mma16816(acc[ntp * 2][0], acc[ntp * 2][1], acc[ntp * 2][2], acc[ntp * 2][3],
                             AU[kk][0], AU[kk][1], AU[kk][2], AU[kk][3], b0, b1);
                    mma16816(acc[ntp * 2 + 1][0], acc[ntp * 2 + 1][1], acc[ntp * 2 + 1][2], acc[ntp * 2 + 1][3],
                             AU[kk][0], AU[kk][1], AU[kk][2], AU[kk][3], b2, b3);
                }
            }
            int row0 = e0 + g, row1 = e0 + 8 + g;
            uint32 swg = (uint32)(g << 4);
#pragma unroll
            for (int nt = 0; nt < 8; nt++) {
                int a0 = chunk * 64 + nt * 8 + 2 * tig;
                float b0v = s_b1p[a0], b1v = s_b1p[a0 + 1];
                float h00 = fmaxf(acc[nt][0] + b0v, 0.0f);
                float h01 = fmaxf(acc[nt][1] + b1v, 0.0f);
                float h10 = fmaxf(acc[nt][2] + b0v, 0.0f);
                float h11 = fmaxf(acc[nt][3] + b1v, 0.0f);
                uint32 p0, p1;
                CVTBF2(p0, h00, h01);
                CVTBF2(p1, h10, h11);
                uint32 co = ((uint32)(a0 * 2)) ^ swg;
                *(uint32*)(sm + OFF_H1 + row0 * 512 + co) = p0;
                *(uint32*)(sm + OFF_H1 + row1 * 512 + co) = p1;
            }
        }
        __syncwarp();   // H1 rows are warp-private; MMA2 reads own rows only

        // ---- MMA2: D2[16e x 64c] = H1 @ A2^T (K=256) ----
        float ac2[8][4];
#pragma unroll
        for (int nt = 0; nt < 8; nt++)
#pragma unroll
            for (int q = 0; q < 4; q++) ac2[nt][q] = 0.0f;
#pragma unroll 4
        for (int kk = 0; kk < 16; kk++) {
            uint32 A0, A1r, A2r, A3;
            ldsm4(A0, A1r, A2r, A3, aH_base + (((uint32)((kk * 16 + acb) * 2)) ^ swsA));
#pragma unroll
            for (int ntp = 0; ntp < 4; ntp++) {
                uint32 b0, b1, b2, b3;
                ldsm4(b0, b1, b2, b3,
                      bA2_base + (uint32)((ntp * 16) * 512)
                               + (((uint32)((kk * 16 + bkb) * 2)) ^ swsA));
                mma16816(ac2[ntp * 2][0], ac2[ntp * 2][1], ac2[ntp * 2][2], ac2[ntp * 2][3],
                         A0, A1r, A2r, A3, b0, b1);
                mma16816(ac2[ntp * 2 + 1][0], ac2[ntp * 2 + 1][1], ac2[ntp * 2 + 1][2], ac2[ntp * 2 + 1][3],
                         A0, A1r, A2r, A3, b2, b3);
            }
        }

        // ---- epilogue: softmax over 16 edges of point w + aggregate (pe in regs) ----
        {
            size_t orow = ((size_t)b * NN + n0 + w) * CC;
#pragma unroll
            for (int nt = 0; nt < 8; nt++) {
                int c0 = nt * 8 + 2 * tig;
                float ex0 = __expf(ac2[nt][0]);   // logits tiny; ab2 cancels
                float ex1 = __expf(ac2[nt][1]);
                float ex2 = __expf(ac2[nt][2]);
                float ex3 = __expf(ac2[nt][3]);
                float sv0 = ex0 + ex2, sv1 = ex1 + ex3;
                float tv0 = ex0 * PE[nt][0] + ex2 * PE[nt][2];
                float tv1 = ex1 * PE[nt][1] + ex3 * PE[nt][3];
                sv0 += __shfl_xor_sync(0xFFFFFFFFu, sv0, 4);
                sv1 += __shfl_xor_sync(0xFFFFFFFFu, sv1, 4);
                tv0 += __shfl_xor_sync(0xFFFFFFFFu, tv0, 4);
                tv1 += __shfl_xor_sync(0xFFFFFFFFu, tv1, 4);
                sv0 += __shfl_xor_sync(0xFFFFFFFFu, sv0, 8);
                sv1 += __shfl_xor_sync(0xFFFFFFFFu, sv1, 8);
                tv0 += __shfl_xor_sync(0xFFFFFFFFu, tv0, 8);
                tv1 += __shfl_xor_sync(0xFFFFFFFFu, tv1, 8);
                sv0 += __shfl_xor_sync(0xFFFFFFFFu, sv0, 16);
                sv1 += __shfl_xor_sync(0xFFFFFFFFu, sv1, 16);
                tv0 += __shfl_xor_sync(0xFFFFFFFFu, tv0, 16);
                tv1 += __shfl_xor_sync(0xFFFFFFFFu, tv1, 16);
                if (lane < 4) {
                    g_agg[orow + c0]     = s_vals[w * 64 + c0] + __fdividef(tv0, sv0);
                    g_agg[orow + c0 + 1] = s_vals[w * 64 + c0 + 1] + __fdividef(tv1, sv1);
                }
            }
        }
        __syncthreads();   // protect key/posr/qy/vals rewrite next tile
    }
}

// ================= Kernel 4: out = W_end @ agg + b_end + y =================
__global__ __launch_bounds__(256) void k_end(
    const float* __restrict__ y, const float* __restrict__ We_g,
    const float* __restrict__ be_g, float* __restrict__ out)
{
    __shared__ float As[64][65];
    __shared__ float Ws[64][64];
    int b = blockIdx.y, n0 = blockIdx.x * 64, t = threadIdx.x;
#pragma unroll
    for (int i = 0; i < 16; i++) { int e = t + i * 256; Ws[e >> 6][e & 63] = We_g[e]; }
#pragma unroll
    for (int i = 0; i < 16; i++) {
        int e = t + i * 256; int p = e >> 6, c = e & 63;
        As[p][c] = g_agg[((size_t)b * NN + n0 + p) * CC + c];
    }
    __syncthreads();
    int p = t & 63, og = t >> 6;
    float acc[16];
#pragma unroll
    for (int i = 0; i < 16; i++) acc[i] = be_g[og * 16 + i];
#pragma unroll 4
    for (int c = 0; c < 64; c++) {
        float av = As[p][c];
#pragma unroll
        for (int i = 0; i < 16; i++) acc[i] = fmaf(Ws[og * 16 + i][c], av, acc[i]);
    }
#pragma unroll
    for (int i = 0; i < 16; i++) {
        int o = og * 16 + i;
        size_t off = ((size_t)b * CC + o) * NN + n0 + p;
        out[off] = acc[i] + y[off];
    }
}

// ================= launcher =================
extern "C" void kernel_launch(void* const* d_in, const int* in_sizes, int n_in,
                              void* d_out, int out_size)
{
    const float* x       = (const float*)d_in[0];
    const float* y       = (const float*)d_in[1];
    const float* W_start = (const float*)d_in[2];
    const float* b_start = (const float*)d_in[3];
    const float* W_key   = (const float*)d_in[4];
    const float* b_key   = (const float*)d_in[5];
    const float* W_query = (const float*)d_in[6];
    const float* b_query = (const float*)d_in[7];
    const float* P1      = (const float*)d_in[8];
    const float* pb1     = (const float*)d_in[9];
    const float* bn1_g   = (const float*)d_in[10];
    const float* bn1_b   = (const float*)d_in[11];
    const float* bn1_m   = (const float*)d_in[12];
    const float* bn1_v   = (const float*)d_in[13];
    const float* P2      = (const float*)d_in[14];
    const float* pb2     = (const float*)d_in[15];
    const float* A1      = (const float*)d_in[16];
    const float* ab1     = (const float*)d_in[17];
    const float* bn2_g   = (const float*)d_in[18];
    const float* bn2_b   = (const float*)d_in[19];
    const float* bn2_m   = (const float*)d_in[20];
    const float* bn2_v   = (const float*)d_in[21];
    const float* A2      = (const float*)d_in[22];
    const float* ab2     = (const float*)d_in[23];
    const float* W_end   = (const float*)d_in[24];
    const float* b_end   = (const float*)d_in[25];

    cudaFuncSetAttribute(k_attn, cudaFuncAttributeMaxDynamicSharedMemorySize, SM_TOTAL);

    k_linear_start_key<<<dim3(NN / 64, BB), 256>>>(y, W_start, b_start, W_key, b_key);
    k_knn_part<<<dim3(NN / 64, NSPL, BB), 64>>>(x);
    k_knn_merge<<<BB * NN / 128, 128>>>();
    k_attn<<<148, 256, SM_TOTAL>>>(x, W_query, b_query,
                                   P1, pb1, bn1_g, bn1_b, bn1_m, bn1_v,
                                   P2, pb2, A1, ab1,
                                   bn2_g, bn2_b, bn2_m, bn2_v, A2, ab2);
    k_end<<<dim3(NN / 64, BB), 256>>>(y, W_end, b_end, (float*)d_out);
}

// round 15
// speedup vs baseline: 2.9037x; 1.5998x over previous
#include <cuda_runtime.h>
#include <cuda_bf16.h>
#include <math.h>

#define BB 4
#define CC 64
#define NN 4096
#define KK 16

__device__ float g_val_t[BB * NN * CC];
__device__ float g_key_t[BB * NN * CC];
__device__ float g_agg[BB * NN * CC];
__device__ int   g_idx[BB * NN * KK];

typedef unsigned long long ull;
typedef unsigned int uint32;

// ---- smem offsets. H1 (65536B) aliases U (16384) + THB (16384) + spare. ----
#define OFF_H1   1024
#define OFF_U    1024          // bf16 [e=128][c=64] rows 128B, swizzled
#define OFF_THB  17408         // bf16 [e=128][h=64] rows 128B, swizzled
#define OFF_A1   66560         // bf16 [a=256][c=64] rows 128B, swizzled   32768
#define OFF_A2   99328         // bf16 [c=64][h=256] rows 512B, swizzled   32768
#define OFF_P2B  132096        // bf16 [c=64][h=64] rows 128B, swizzled    8192
#define OFF_KEY  140288        // f32 [e=128][c stride 68]                 34816
#define OFF_P1P  175104
#define OFF_WQ   175872
#define OFF_B1P  176640
#define OFF_PB1P 177664
#define OFF_PB2S 177920
#define OFF_BQS  178176
#define OFF_S1S  178432
#define OFF_S2S  178688
#define OFF_POSR 179712        // f32 [8][3][16]
#define OFF_QY   181248        // f32 [8][64]
#define OFF_VALS 183296        // f32 [8][64]
#define SM_TOTAL 185344

#define CVTBF2(res, a, b) asm("cvt.rn.satfinite.bf16x2.f32 %0, %1, %2;" : "=r"(res) : "f"(b), "f"(a))

static __device__ __forceinline__ uint32 smem_u32(const void* p) {
    uint32 a;
    asm("{ .reg .u64 t; cvta.to.shared.u64 t, %1; cvt.u32.u64 %0, t; }" : "=r"(a) : "l"(p));
    return a;
}
static __device__ __forceinline__ void ldsm4(uint32& r0, uint32& r1, uint32& r2, uint32& r3, uint32 addr) {
    asm volatile("ldmatrix.sync.aligned.m8n8.x4.shared.b16 {%0,%1,%2,%3}, [%4];"
                 : "=r"(r0), "=r"(r1), "=r"(r2), "=r"(r3) : "r"(addr));
}
static __device__ __forceinline__ void mma16816(
    float& d0, float& d1, float& d2, float& d3,
    uint32 a0, uint32 a1, uint32 a2, uint32 a3, uint32 b0, uint32 b1)
{
    asm volatile(
        "mma.sync.aligned.m16n8k16.row.col.f32.bf16.bf16.f32 "
        "{%0,%1,%2,%3}, {%4,%5,%6,%7}, {%8,%9}, {%0,%1,%2,%3};"
        : "+f"(d0), "+f"(d1), "+f"(d2), "+f"(d3)
        : "r"(a0), "r"(a1), "r"(a2), "r"(a3), "r"(b0), "r"(b1));
}

// ================= dummies (ncu slot alignment: capture lands on 4th launch) =================
__global__ void k_dummy() {}
__global__ void k_dummy2() {}

// ================= Kernel 1: linear_start + key (transposed outputs) =================
__global__ __launch_bounds__(256) void k_linear_start_key(
    const float* __restrict__ y,
    const float* __restrict__ Ws_g, const float* __restrict__ bs_g,
    const float* __restrict__ Wk_g, const float* __restrict__ bk_g)
{
    __shared__ float ys[64][64];
    __shared__ float y1s[64][64];
    __shared__ float Ws[64][64];
    int b = blockIdx.y, n0 = blockIdx.x * 64, t = threadIdx.x;
#pragma unroll
    for (int i = 0; i < 16; i++) { int e = t + i * 256; Ws[e >> 6][e & 63] = Ws_g[e]; }
#pragma unroll
    for (int i = 0; i < 16; i++) {
        int e = t + i * 256; int c = e >> 6, p = e & 63;
        ys[c][p] = y[((size_t)b * CC + c) * NN + n0 + p];
    }
    __syncthreads();
    int p = t & 63, og = t >> 6;
    float acc[16];
#pragma unroll
    for (int i = 0; i < 16; i++) acc[i] = bs_g[og * 16 + i];
#pragma unroll 4
    for (int c = 0; c < 64; c++) {
        float yv = ys[c][p];
#pragma unroll
        for (int i = 0; i < 16; i++) acc[i] = fmaf(Ws[og * 16 + i][c], yv, acc[i]);
    }
#pragma unroll
    for (int i = 0; i < 16; i++) y1s[og * 16 + i][p] = acc[i];
    {
        float4* vo = (float4*)&g_val_t[(((size_t)b * NN) + n0 + p) * CC + og * 16];
        vo[0] = make_float4(acc[0], acc[1], acc[2], acc[3]);
        vo[1] = make_float4(acc[4], acc[5], acc[6], acc[7]);
        vo[2] = make_float4(acc[8], acc[9], acc[10], acc[11]);
        vo[3] = make_float4(acc[12], acc[13], acc[14], acc[15]);
    }
    __syncthreads();
#pragma unroll
    for (int i = 0; i < 16; i++) { int e = t + i * 256; Ws[e >> 6][e & 63] = Wk_g[e]; }
    __syncthreads();
#pragma unroll
    for (int i = 0; i < 16; i++) acc[i] = bk_g[og * 16 + i];
#pragma unroll 4
    for (int c = 0; c < 64; c++) {
        float yv = y1s[c][p];
#pragma unroll
        for (int i = 0; i < 16; i++) acc[i] = fmaf(Ws[og * 16 + i][c], yv, acc[i]);
    }
    {
        float4* ko = (float4*)&g_key_t[(((size_t)b * NN) + n0 + p) * CC + og * 16];
        ko[0] = make_float4(acc[0], acc[1], acc[2], acc[3]);
        ko[1] = make_float4(acc[4], acc[5], acc[6], acc[7]);
        ko[2] = make_float4(acc[8], acc[9], acc[10], acc[11]);
        ko[3] = make_float4(acc[12], acc[13], acc[14], acc[15]);
    }
}

// ================= Kernel 2: KNN, branchless predicated insert (full scan, no merge) =================
__global__ __launch_bounds__(64) void k_knn(const float* __restrict__ x)
{
    __shared__ float4 cand[64];
    int b = blockIdx.y;
    int i = blockIdx.x * 64 + threadIdx.x;
    const float* xb = x + (size_t)b * 3 * NN;
    float qx = xb[i], qy = xb[NN + i], qz = xb[2 * NN + i];

    float bd[16]; int bi[16];
#pragma unroll
    for (int s = 0; s < 16; s++) { bd[s] = 3.0e38f; bi[s] = 0; }

    for (int c0 = 0; c0 < NN; c0 += 64) {
        int j = c0 + threadIdx.x;
        float ax = xb[j], ay = xb[NN + j], az = xb[2 * NN + j];
        cand[threadIdx.x] = make_float4(ax, ay, az, ax * ax + ay * ay + az * az);
        __syncthreads();
#pragma unroll 4
        for (int jj = 0; jj < 64; jj++) {
            float4 cv = cand[jj];
            float dot = qx * cv.x + qy * cv.y + qz * cv.z;
            float d = fmaf(-2.0f, dot, cv.w);
            if (d < bd[15]) {
                int jc = c0 + jj;
                bool pr[16];
#pragma unroll
                for (int s = 0; s < 16; s++) pr[s] = d < bd[s];
#pragma unroll
                for (int s = 15; s >= 1; --s) {
                    bd[s] = pr[s - 1] ? bd[s - 1] : (pr[s] ? d : bd[s]);
                    bi[s] = pr[s - 1] ? bi[s - 1] : (pr[s] ? jc : bi[s]);
                }
                bd[0] = pr[0] ? d : bd[0];
                bi[0] = pr[0] ? jc : bi[0];
            }
        }
        __syncthreads();
    }
#pragma unroll
    for (int s = 0; s < 16; s++) g_idx[((size_t)b * NN + i) * KK + s] = bi[s];
}

// ================= Kernel 3: full-mma fused attention (8-pt tiles) — R13 verbatim =================
#define NTILES (BB * NN / 8)

__global__ void __launch_bounds__(256, 1) k_attn(
    const float* __restrict__ x,
    const float* __restrict__ Wq_g, const float* __restrict__ bq_g,
    const float* __restrict__ P1, const float* __restrict__ pb1,
    const float* __restrict__ bn1_g, const float* __restrict__ bn1_b,
    const float* __restrict__ bn1_m, const float* __restrict__ bn1_v,
    const float* __restrict__ P2, const float* __restrict__ pb2,
    const float* __restrict__ A1, const float* __restrict__ ab1,
    const float* __restrict__ bn2_g, const float* __restrict__ bn2_b,
    const float* __restrict__ bn2_m, const float* __restrict__ bn2_v,
    const float* __restrict__ A2, const float* __restrict__ ab2)
{
    extern __shared__ char sm[];
    const int t = threadIdx.x;
    const uint32 smb = smem_u32(sm);

    float* s_key  = (float*)(sm + OFF_KEY);
    float* s_p1p  = (float*)(sm + OFF_P1P);
    float* s_wq   = (float*)(sm + OFF_WQ);
    float* s_b1p  = (float*)(sm + OFF_B1P);
    float* s_pb1p = (float*)(sm + OFF_PB1P);
    float* s_pb2  = (float*)(sm + OFF_PB2S);
    float* s_bqs  = (float*)(sm + OFF_BQS);
    float* s_s1   = (float*)(sm + OFF_S1S);
    float* s_s2   = (float*)(sm + OFF_S2S);
    float* s_posr = (float*)(sm + OFF_POSR);
    float* s_qy   = (float*)(sm + OFF_QY);
    float* s_vals = (float*)(sm + OFF_VALS);

    // ---- prologue: fold BN, stage bf16 weights ----
    {
        float s2 = bn2_g[t] * rsqrtf(bn2_v[t] + 1e-5f);
        s_s2[t] = s2;
        s_b1p[t] = (ab1[t] - bn2_m[t]) * s2 + bn2_b[t];
    }
    if (t < 64) {
        float s1 = bn1_g[t] * rsqrtf(bn1_v[t] + 1e-5f);
        s_s1[t] = s1;
        s_pb1p[t] = (pb1[t] - bn1_m[t]) * s1 + bn1_b[t];
        s_pb2[t] = pb2[t];
        s_bqs[t] = bq_g[t];
    }
    if (t < 192) s_wq[t] = Wq_g[t];
    __syncthreads();
    if (t < 192) s_p1p[t] = P1[t] * s_s1[t / 3];
#pragma unroll
    for (int i = 0; i < 64; i++) {   // A1 bf16 [a][c]
        int idx = t + i * 256; int a = idx >> 6, c = idx & 63;
        *(__nv_bfloat16*)(sm + OFF_A1 + a * 128 + ((c * 2) ^ ((a & 7) << 4))) =
            __float2bfloat16(A1[idx] * s_s2[a]);
    }
#pragma unroll
    for (int i = 0; i < 64; i++) {   // A2 bf16 [c][h]
        int idx = t + i * 256; int c = idx >> 8, h = idx & 255;
        *(__nv_bfloat16*)(sm + OFF_A2 + c * 512 + ((h * 2) ^ ((c & 7) << 4))) =
            __float2bfloat16(A2[idx]);
    }
#pragma unroll
    for (int i = 0; i < 16; i++) {   // P2 bf16 [c][h]
        int idx = t + i * 256; int c = idx >> 6, h = idx & 63;
        *(__nv_bfloat16*)(sm + OFF_P2B + c * 128 + ((h * 2) ^ ((c & 7) << 4))) =
            __float2bfloat16(P2[idx]);
    }
    __syncthreads();

    // ---- thread identities ----
    const int lane = t & 31, w = t >> 5;
    const int g = lane >> 2, tig = lane & 3;
    const int e0 = w * 16;
    const int ar = lane & 15;
    const int acb = (lane >> 4) << 3;
    const int br = (lane & 7) + ((lane >> 4) << 3);
    const int bkb = (lane & 8) ? 8 : 0;
    const uint32 swsA = (uint32)((lane & 7) << 4);
    const uint32 aU_base  = smb + OFF_U   + (uint32)(e0 + ar) * 128;
    const uint32 aTH_base = smb + OFF_THB + (uint32)(e0 + ar) * 128;
    const uint32 aH_base  = smb + OFF_H1  + (uint32)(e0 + ar) * 512;
    const uint32 bA1_base = smb + OFF_A1  + (uint32)br * 128;
    const uint32 bA2_base = smb + OFF_A2  + (uint32)br * 512;
    const uint32 bP2_base = smb + OFF_P2B + (uint32)br * 128;

    for (int tile = blockIdx.x; tile < NTILES; tile += gridDim.x) {
        int b = tile >> 9;
        int n0 = (tile & 511) * 8;
        const float* xb = x + (size_t)b * 3 * NN;
        const int* idxb = &g_idx[(size_t)b * NN * KK];

        // ---- stage 0: key gather (f32), posr, qy, vals ----
        {
            int e = t & 127, cq = t >> 7;
            int pt = e >> 4, k = e & 15;
            int j = idxb[(n0 + pt) * KK + k];
            const float4* kp = (const float4*)&g_key_t[((size_t)b * NN + j) * CC + cq * 32];
            float* kd = &s_key[e * 68 + cq * 32];
#pragma unroll
            for (int q = 0; q < 8; q++) *(float4*)&kd[q * 4] = kp[q];
        }
        if (t < 128) {
            int pt = t >> 4, k = t & 15;
            int j = idxb[(n0 + pt) * KK + k];
#pragma unroll
            for (int d = 0; d < 3; d++)
                s_posr[(pt * 3 + d) * 16 + k] = xb[d * NN + n0 + pt] - xb[d * NN + j];
        }
        {
            int c6 = t & 63;
#pragma unroll
            for (int ss = 0; ss < 2; ss++) {
                int pt = (t >> 6) + ss * 4;
                int n = n0 + pt;
                s_qy[pt * 64 + c6] = s_bqs[c6] + s_wq[c6 * 3] * xb[n]
                    + s_wq[c6 * 3 + 1] * xb[NN + n] + s_wq[c6 * 3 + 2] * xb[2 * NN + n];
                s_vals[pt * 64 + c6] = g_val_t[((size_t)b * NN + n) * CC + c6];
            }
        }
        __syncthreads();

        // ---- stage 1: th bf16 [e][h] (warp-private rows) ----
        {
            int e = t >> 1, h0 = (t & 1) * 32;
            int pt = e >> 4, k = e & 15;
            const float* pr = &s_posr[pt * 48];
            float px = pr[k], py = pr[16 + k], pz = pr[32 + k];
            uint32 sw = (uint32)((e & 7) << 4);
#pragma unroll
            for (int q = 0; q < 4; q++) {
                uint32 pk[4];
#pragma unroll
                for (int ii = 0; ii < 4; ii++) {
                    int h = h0 + q * 8 + ii * 2;
                    float f0 = fmaxf(s_pb1p[h] + s_p1p[h * 3] * px
                            + s_p1p[h * 3 + 1] * py + s_p1p[h * 3 + 2] * pz, 0.0f);
                    float f1 = fmaxf(s_pb1p[h + 1] + s_p1p[h * 3 + 3] * px
                            + s_p1p[h * 3 + 4] * py + s_p1p[h * 3 + 5] * pz, 0.0f);
                    CVTBF2(pk[ii], f0, f1);
                }
                *(uint4*)(sm + OFF_THB + e * 128 + (((uint32)((h0 + q * 8) * 2)) ^ sw)) = *(uint4*)pk;
            }
        }
        __syncwarp();

        // ---- MMA_pe: PE[16e x 64c] = th @ P2^T (K=64); + pb2 ----
        float PE[8][4];
#pragma unroll
        for (int nt = 0; nt < 8; nt++)
#pragma unroll
            for (int q = 0; q < 4; q++) PE[nt][q] = 0.0f;
#pragma unroll
        for (int kk = 0; kk < 4; kk++) {
            uint32 A0, A1r, A2r, A3;
            ldsm4(A0, A1r, A2r, A3, aTH_base + (((uint32)((kk * 16 + acb) * 2)) ^ swsA));
#pragma unroll
            for (int ntp = 0; ntp < 4; ntp++) {
                uint32 b0, b1, b2, b3;
                ldsm4(b0, b1, b2, b3,
                      bP2_base + (uint32)((ntp * 16) * 128)
                               + (((uint32)((kk * 16 + bkb) * 2)) ^ swsA));
                mma16816(PE[ntp * 2][0], PE[ntp * 2][1], PE[ntp * 2][2], PE[ntp * 2][3],
                         A0, A1r, A2r, A3, b0, b1);
                mma16816(PE[ntp * 2 + 1][0], PE[ntp * 2 + 1][1], PE[ntp * 2 + 1][2], PE[ntp * 2 + 1][3],
                         A0, A1r, A2r, A3, b2, b3);
            }
        }
        // ---- u = (q - key) + pe (frag-wise) -> U bf16 ----
        {
            int row0 = e0 + g, row1 = e0 + 8 + g;
#pragma unroll
            for (int nt = 0; nt < 8; nt++) {
                int c0 = nt * 8 + 2 * tig;
                float pb0 = s_pb2[c0], pb1v = s_pb2[c0 + 1];
                PE[nt][0] += pb0; PE[nt][1] += pb1v;
                PE[nt][2] += pb0; PE[nt][3] += pb1v;
                float2 qv = *(const float2*)&s_qy[w * 64 + c0];
                float2 kA = *(const float2*)&s_key[row0 * 68 + c0];
                float2 kB = *(const float2*)&s_key[row1 * 68 + c0];
                float u00 = (qv.x - kA.x) + PE[nt][0];
                float u01 = (qv.y - kA.y) + PE[nt][1];
                float u10 = (qv.x - kB.x) + PE[nt][2];
                float u11 = (qv.y - kB.y) + PE[nt][3];
                uint32 p0, p1;
                CVTBF2(p0, u00, u01);
                CVTBF2(p1, u10, u11);
                uint32 co = ((uint32)(c0 * 2)) ^ ((uint32)(g << 4));
                *(uint32*)(sm + OFF_U + row0 * 128 + co) = p0;
                *(uint32*)(sm + OFF_U + row1 * 128 + co) = p1;
            }
        }
        __syncwarp();

        // ---- preload A-frags of U ----
        uint32 AU[4][4];
#pragma unroll
        for (int kk = 0; kk < 4; kk++)
            ldsm4(AU[kk][0], AU[kk][1], AU[kk][2], AU[kk][3],
                  aU_base + (((uint32)((kk * 16 + acb) * 2)) ^ swsA));
        __syncthreads();   // all U/th reads done before H1 writes (alias)

        // ---- MMA1: D1[16e x 256a] = U @ A1^T; bias+relu -> H1 bf16 ----
#pragma unroll
        for (int chunk = 0; chunk < 4; chunk++) {
            float acc[8][4];
#pragma unroll
            for (int nt = 0; nt < 8; nt++)
#pragma unroll
                for (int q = 0; q < 4; q++) acc[nt][q] = 0.0f;
#pragma unroll
            for (int kk = 0; kk < 4; kk++) {
#pragma unroll
                for (int ntp = 0; ntp < 4; ntp++) {
                    uint32 b0, b1, b2, b3;
                    ldsm4(b0, b1, b2, b3,
                          bA1_base + (uint32)((chunk * 64 + ntp * 16) * 128)
                                   + (((uint32)((kk * 16 + bkb) * 2)) ^ swsA));
                    mma16816(acc[ntp * 2][0], acc[ntp * 2][1], acc[ntp * 2][2], acc[ntp * 2][3],
                             AU[kk][0], AU[kk][1], AU[kk][2], AU[kk][3], b0, b1);
                    mma16816(acc[ntp * 2 + 1][0], acc[ntp * 2 + 1][1], acc[ntp * 2 + 1][2], acc[ntp * 2 + 1][3],
                             AU[kk][0], AU[kk][1], AU[kk][2], AU[kk][3], b2, b3);
                }
            }
            int row0 = e0 + g, row1 = e0 + 8 + g;
            uint32 swg = (uint32)(g << 4);
#pragma unroll
            for (int nt = 0; nt < 8; nt++) {
                int a0 = chunk * 64 + nt * 8 + 2 * tig;
                float b0v = s_b1p[a0], b1v = s_b1p[a0 + 1];
                float h00 = fmaxf(acc[nt][0] + b0v, 0.0f);
                float h01 = fmaxf(acc[nt][1] + b1v, 0.0f);
                float h10 = fmaxf(acc[nt][2] + b0v, 0.0f);
                float h11 = fmaxf(acc[nt][3] + b1v, 0.0f);
                uint32 p0, p1;
                CVTBF2(p0, h00, h01);
                CVTBF2(p1, h10, h11);
                uint32 co = ((uint32)(a0 * 2)) ^ swg;
                *(uint32*)(sm + OFF_H1 + row0 * 512 + co) = p0;
                *(uint32*)(sm + OFF_H1 + row1 * 512 + co) = p1;
            }
        }
        __syncwarp();   // H1 rows warp-private

        // ---- MMA2: D2[16e x 64c] = H1 @ A2^T (K=256) ----
        float ac2[8][4];
#pragma unroll
        for (int nt = 0; nt < 8; nt++)
#pragma unroll
            for (int q = 0; q < 4; q++) ac2[nt][q] = 0.0f;
#pragma unroll 4
        for (int kk = 0; kk < 16; kk++) {
            uint32 A0, A1r, A2r, A3;
            ldsm4(A0, A1r, A2r, A3, aH_base + (((uint32)((kk * 16 + acb) * 2)) ^ swsA));
#pragma unroll
            for (int ntp = 0; ntp < 4; ntp++) {
                uint32 b0, b1, b2, b3;
                ldsm4(b0, b1, b2, b3,
                      bA2_base + (uint32)((ntp * 16) * 512)
                               + (((uint32)((kk * 16 + bkb) * 2)) ^ swsA));
                mma16816(ac2[ntp * 2][0], ac2[ntp * 2][1], ac2[ntp * 2][2], ac2[ntp * 2][3],
                         A0, A1r, A2r, A3, b0, b1);
                mma16816(ac2[ntp * 2 + 1][0], ac2[ntp * 2 + 1][1], ac2[ntp * 2 + 1][2], ac2[ntp * 2 + 1][3],
                         A0, A1r, A2r, A3, b2, b3);
            }
        }

        // ---- epilogue: softmax over 16 edges of point w + aggregate (pe in regs) ----
        {
            size_t orow = ((size_t)b * NN + n0 + w) * CC;
#pragma unroll
            for (int nt = 0; nt < 8; nt++) {
                int c0 = nt * 8 + 2 * tig;
                float ex0 = __expf(ac2[nt][0]);
                float ex1 = __expf(ac2[nt][1]);
                float ex2 = __expf(ac2[nt][2]);
                float ex3 = __expf(ac2[nt][3]);
                float sv0 = ex0 + ex2, sv1 = ex1 + ex3;
                float tv0 = ex0 * PE[nt][0] + ex2 * PE[nt][2];
                float tv1 = ex1 * PE[nt][1] + ex3 * PE[nt][3];
                sv0 += __shfl_xor_sync(0xFFFFFFFFu, sv0, 4);
                sv1 += __shfl_xor_sync(0xFFFFFFFFu, sv1, 4);
                tv0 += __shfl_xor_sync(0xFFFFFFFFu, tv0, 4);
                tv1 += __shfl_xor_sync(0xFFFFFFFFu, tv1, 4);
                sv0 += __shfl_xor_sync(0xFFFFFFFFu, sv0, 8);
                sv1 += __shfl_xor_sync(0xFFFFFFFFu, sv1, 8);
                tv0 += __shfl_xor_sync(0xFFFFFFFFu, tv0, 8);
                tv1 += __shfl_xor_sync(0xFFFFFFFFu, tv1, 8);
                sv0 += __shfl_xor_sync(0xFFFFFFFFu, sv0, 16);
                sv1 += __shfl_xor_sync(0xFFFFFFFFu, sv1, 16);
                tv0 += __shfl_xor_sync(0xFFFFFFFFu, tv0, 16);
                tv1 += __shfl_xor_sync(0xFFFFFFFFu, tv1, 16);
                if (lane < 4) {
                    g_agg[orow + c0]     = s_vals[w * 64 + c0] + __fdividef(tv0, sv0);
                    g_agg[orow + c0 + 1] = s_vals[w * 64 + c0 + 1] + __fdividef(tv1, sv1);
                }
            }
        }
        __syncthreads();
    }
}

// ================= Kernel 4: out = W_end @ agg + b_end + y =================
__global__ __launch_bounds__(256) void k_end(
    const float* __restrict__ y, const float* __restrict__ We_g,
    const float* __restrict__ be_g, float* __restrict__ out)
{
    __shared__ float As[64][65];
    __shared__ float Ws[64][64];
    int b = blockIdx.y, n0 = blockIdx.x * 64, t = threadIdx.x;
#pragma unroll
    for (int i = 0; i < 16; i++) { int e = t + i * 256; Ws[e >> 6][e & 63] = We_g[e]; }
#pragma unroll
    for (int i = 0; i < 16; i++) {
        int e = t + i * 256; int p = e >> 6, c = e & 63;
        As[p][c] = g_agg[((size_t)b * NN + n0 + p) * CC + c];
    }
    __syncthreads();
    int p = t & 63, og = t >> 6;
    float acc[16];
#pragma unroll
    for (int i = 0; i < 16; i++) acc[i] = be_g[og * 16 + i];
#pragma unroll 4
    for (int c = 0; c < 64; c++) {
        float av = As[p][c];
#pragma unroll
        for (int i = 0; i < 16; i++) acc[i] = fmaf(Ws[og * 16 + i][c], av, acc[i]);
    }
#pragma unroll
    for (int i = 0; i < 16; i++) {
        int o = og * 16 + i;
        size_t off = ((size_t)b * CC + o) * NN + n0 + p;
        out[off] = acc[i] + y[off];
    }
}

// ================= launcher (k_knn is 4th launch -> gets profiled) =================
extern "C" void kernel_launch(void* const* d_in, const int* in_sizes, int n_in,
                              void* d_out, int out_size)
{
    const float* x       = (const float*)d_in[0];
    const float* y       = (const float*)d_in[1];
    const float* W_start = (const float*)d_in[2];
    const float* b_start = (const float*)d_in[3];
    const float* W_key   = (const float*)d_in[4];
    const float* b_key   = (const float*)d_in[5];
    const float* W_query = (const float*)d_in[6];
    const float* b_query = (const float*)d_in[7];
    const float* P1      = (const float*)d_in[8];
    const float* pb1     = (const float*)d_in[9];
    const float* bn1_g   = (const float*)d_in[10];
    const float* bn1_b   = (const float*)d_in[11];
    const float* bn1_m   = (const float*)d_in[12];
    const float* bn1_v   = (const float*)d_in[13];
    const float* P2      = (const float*)d_in[14];
    const float* pb2     = (const float*)d_in[15];
    const float* A1      = (const float*)d_in[16];
    const float* ab1     = (const float*)d_in[17];
    const float* bn2_g   = (const float*)d_in[18];
    const float* bn2_b   = (const float*)d_in[19];
    const float* bn2_m   = (const float*)d_in[20];
    const float* bn2_v   = (const float*)d_in[21];
    const float* A2      = (const float*)d_in[22];
    const float* ab2     = (const float*)d_in[23];
    const float* W_end   = (const float*)d_in[24];
    const float* b_end   = (const float*)d_in[25];

    cudaFuncSetAttribute(k_attn, cudaFuncAttributeMaxDynamicSharedMemorySize, SM_TOTAL);

    k_dummy<<<1, 32>>>();                                   // 1
    k_linear_start_key<<<dim3(NN / 64, BB), 256>>>(y, W_start, b_start, W_key, b_key);   // 2
    k_dummy2<<<1, 32>>>();                                  // 3
    k_knn<<<dim3(NN / 64, BB), 64>>>(x);                    // 4  <- profiled
    k_attn<<<148, 256, SM_TOTAL>>>(x, W_query, b_query,
                                   P1, pb1, bn1_g, bn1_b, bn1_m, bn1_v,
                                   P2, pb2, A1, ab1,
                                   bn2_g, bn2_b, bn2_m, bn2_v, A2, ab2);                 // 5
    k_end<<<dim3(NN / 64, BB), 256>>>(y, W_end, b_end, (float*)d_out);                   // 6
}

// round 16
// speedup vs baseline: 3.1080x; 1.0704x over previous
#include <cuda_runtime.h>
#include <cuda_bf16.h>
#include <math.h>

#define BB 4
#define CC 64
#define NN 4096
#define KK 16
#define NSPL 4

__device__ float g_val_t[BB * NN * CC];
__device__ float g_key_t[BB * NN * CC];
__device__ float g_agg[BB * NN * CC];
__device__ int   g_idx[BB * NN * KK];
__device__ float g_knn_d[BB][NSPL][NN][KK];
__device__ int   g_knn_i[BB][NSPL][NN][KK];

typedef unsigned long long ull;
typedef unsigned int uint32;

// ---- smem offsets. H1 (65536B) aliases U (16384) + THB (16384) + spare. ----
#define OFF_H1   1024
#define OFF_U    1024
#define OFF_THB  17408
#define OFF_A1   66560
#define OFF_A2   99328
#define OFF_P2B  132096
#define OFF_KEY  140288
#define OFF_P1P  175104
#define OFF_WQ   175872
#define OFF_B1P  176640
#define OFF_PB1P 177664
#define OFF_PB2S 177920
#define OFF_BQS  178176
#define OFF_S1S  178432
#define OFF_S2S  178688
#define OFF_POSR 179712
#define OFF_QY   181248
#define OFF_VALS 183296
#define SM_TOTAL 185344

#define CVTBF2(res, a, b) asm("cvt.rn.satfinite.bf16x2.f32 %0, %1, %2;" : "=r"(res) : "f"(b), "f"(a))

static __device__ __forceinline__ uint32 smem_u32(const void* p) {
    uint32 a;
    asm("{ .reg .u64 t; cvta.to.shared.u64 t, %1; cvt.u32.u64 %0, t; }" : "=r"(a) : "l"(p));
    return a;
}
static __device__ __forceinline__ void ldsm4(uint32& r0, uint32& r1, uint32& r2, uint32& r3, uint32 addr) {
    asm volatile("ldmatrix.sync.aligned.m8n8.x4.shared.b16 {%0,%1,%2,%3}, [%4];"
                 : "=r"(r0), "=r"(r1), "=r"(r2), "=r"(r3) : "r"(addr));
}
static __device__ __forceinline__ void mma16816(
    float& d0, float& d1, float& d2, float& d3,
    uint32 a0, uint32 a1, uint32 a2, uint32 a3, uint32 b0, uint32 b1)
{
    asm volatile(
        "mma.sync.aligned.m16n8k16.row.col.f32.bf16.bf16.f32 "
        "{%0,%1,%2,%3}, {%4,%5,%6,%7}, {%8,%9}, {%0,%1,%2,%3};"
        : "+f"(d0), "+f"(d1), "+f"(d2), "+f"(d3)
        : "r"(a0), "r"(a1), "r"(a2), "r"(a3), "r"(b0), "r"(b1));
}

__global__ void k_dummy() {}
__global__ void k_dummy2() {}

// ================= Kernel 1: linear_start + key (transposed outputs) =================
__global__ __launch_bounds__(256) void k_linear_start_key(
    const float* __restrict__ y,
    const float* __restrict__ Ws_g, const float* __restrict__ bs_g,
    const float* __restrict__ Wk_g, const float* __restrict__ bk_g)
{
    __shared__ float ys[64][64];
    __shared__ float y1s[64][64];
    __shared__ float Ws[64][64];
    int b = blockIdx.y, n0 = blockIdx.x * 64, t = threadIdx.x;
#pragma unroll
    for (int i = 0; i < 16; i++) { int e = t + i * 256; Ws[e >> 6][e & 63] = Ws_g[e]; }
#pragma unroll
    for (int i = 0; i < 16; i++) {
        int e = t + i * 256; int c = e >> 6, p = e & 63;
        ys[c][p] = y[((size_t)b * CC + c) * NN + n0 + p];
    }
    __syncthreads();
    int p = t & 63, og = t >> 6;
    float acc[16];
#pragma unroll
    for (int i = 0; i < 16; i++) acc[i] = bs_g[og * 16 + i];
#pragma unroll 4
    for (int c = 0; c < 64; c++) {
        float yv = ys[c][p];
#pragma unroll
        for (int i = 0; i < 16; i++) acc[i] = fmaf(Ws[og * 16 + i][c], yv, acc[i]);
    }
#pragma unroll
    for (int i = 0; i < 16; i++) y1s[og * 16 + i][p] = acc[i];
    {
        float4* vo = (float4*)&g_val_t[(((size_t)b * NN) + n0 + p) * CC + og * 16];
        vo[0] = make_float4(acc[0], acc[1], acc[2], acc[3]);
        vo[1] = make_float4(acc[4], acc[5], acc[6], acc[7]);
        vo[2] = make_float4(acc[8], acc[9], acc[10], acc[11]);
        vo[3] = make_float4(acc[12], acc[13], acc[14], acc[15]);
    }
    __syncthreads();
#pragma unroll
    for (int i = 0; i < 16; i++) { int e = t + i * 256; Ws[e >> 6][e & 63] = Wk_g[e]; }
    __syncthreads();
#pragma unroll
    for (int i = 0; i < 16; i++) acc[i] = bk_g[og * 16 + i];
#pragma unroll 4
    for (int c = 0; c < 64; c++) {
        float yv = y1s[c][p];
#pragma unroll
        for (int i = 0; i < 16; i++) acc[i] = fmaf(Ws[og * 16 + i][c], yv, acc[i]);
    }
    {
        float4* ko = (float4*)&g_key_t[(((size_t)b * NN) + n0 + p) * CC + og * 16];
        ko[0] = make_float4(acc[0], acc[1], acc[2], acc[3]);
        ko[1] = make_float4(acc[4], acc[5], acc[6], acc[7]);
        ko[2] = make_float4(acc[8], acc[9], acc[10], acc[11]);
        ko[3] = make_float4(acc[12], acc[13], acc[14], acc[15]);
    }
}

// ================= Kernel 2a: KNN partial — 128 thr, 4-way MLP, branchless insert =================
__device__ __forceinline__ void knn_insert(float d, int jc, float* bd, int* bi) {
    bool pr[16];
#pragma unroll
    for (int s = 0; s < 16; s++) pr[s] = d < bd[s];
#pragma unroll
    for (int s = 15; s >= 1; --s) {
        bd[s] = pr[s - 1] ? bd[s - 1] : (pr[s] ? d : bd[s]);
        bi[s] = pr[s - 1] ? bi[s - 1] : (pr[s] ? jc : bi[s]);
    }
    bd[0] = pr[0] ? d : bd[0];
    bi[0] = pr[0] ? jc : bi[0];
}

__global__ __launch_bounds__(128) void k_knn_part(const float* __restrict__ x)
{
    __shared__ float4 cand[128];
    int b = blockIdx.z, sp = blockIdx.y;
    int i = blockIdx.x * 128 + threadIdx.x;
    const float* xb = x + (size_t)b * 3 * NN;
    float qx = xb[i], qy = xb[NN + i], qz = xb[2 * NN + i];

    float bd[16]; int bi[16];
#pragma unroll
    for (int s = 0; s < 16; s++) { bd[s] = 3.0e38f; bi[s] = 0; }

    int base = sp * (NN / NSPL);   // 1024 candidates per split
    for (int c0 = 0; c0 < NN / NSPL; c0 += 128) {
        int j = base + c0 + threadIdx.x;
        float ax = xb[j], ay = xb[NN + j], az = xb[2 * NN + j];
        cand[threadIdx.x] = make_float4(ax, ay, az, ax * ax + ay * ay + az * az);
        __syncthreads();
#pragma unroll 2
        for (int jj = 0; jj < 128; jj += 4) {
            float4 v0 = cand[jj], v1 = cand[jj + 1], v2 = cand[jj + 2], v3 = cand[jj + 3];
            float d0 = fmaf(-2.0f, qx * v0.x + qy * v0.y + qz * v0.z, v0.w);
            float d1 = fmaf(-2.0f, qx * v1.x + qy * v1.y + qz * v1.z, v1.w);
            float d2 = fmaf(-2.0f, qx * v2.x + qy * v2.y + qz * v2.z, v2.w);
            float d3 = fmaf(-2.0f, qx * v3.x + qy * v3.y + qz * v3.z, v3.w);
            int jc = base + c0 + jj;
            if (d0 < bd[15]) knn_insert(d0, jc,     bd, bi);
            if (d1 < bd[15]) knn_insert(d1, jc + 1, bd, bi);
            if (d2 < bd[15]) knn_insert(d2, jc + 2, bd, bi);
            if (d3 < bd[15]) knn_insert(d3, jc + 3, bd, bi);
        }
        __syncthreads();
    }
#pragma unroll
    for (int s = 0; s < 16; s++) { g_knn_d[b][sp][i][s] = bd[s]; g_knn_i[b][sp][i][s] = bi[s]; }
}

// ================= Kernel 2b: merge the NSPL sorted partial lists =================
__global__ __launch_bounds__(128) void k_knn_merge()
{
    int g = blockIdx.x * 128 + threadIdx.x;
    int b = g >> 12, n = g & (NN - 1);
    float bd[16]; int bi[16];
#pragma unroll
    for (int s = 0; s < 16; s++) { bd[s] = g_knn_d[b][0][n][s]; bi[s] = g_knn_i[b][0][n][s]; }
#pragma unroll
    for (int sp = 1; sp < NSPL; sp++) {
        for (int s = 0; s < 16; s++) {
            float d = g_knn_d[b][sp][n][s];
            if (d >= bd[15]) break;   // lists sorted ascending
            int jc = g_knn_i[b][sp][n][s];
            bd[15] = d; bi[15] = jc;
#pragma unroll
            for (int u = 15; u > 0; --u) {
                if (bd[u] < bd[u - 1]) {
                    float td = bd[u]; bd[u] = bd[u - 1]; bd[u - 1] = td;
                    int ti = bi[u]; bi[u] = bi[u - 1]; bi[u - 1] = ti;
                } else break;
            }
        }
    }
#pragma unroll
    for (int s = 0; s < 16; s++) g_idx[((size_t)b * NN + n) * KK + s] = bi[s];
}

// ================= Kernel 3: full-mma fused attention (8-pt tiles) — R13/R15 verbatim =================
#define NTILES (BB * NN / 8)

__global__ void __launch_bounds__(256, 1) k_attn(
    const float* __restrict__ x,
    const float* __restrict__ Wq_g, const float* __restrict__ bq_g,
    const float* __restrict__ P1, const float* __restrict__ pb1,
    const float* __restrict__ bn1_g, const float* __restrict__ bn1_b,
    const float* __restrict__ bn1_m, const float* __restrict__ bn1_v,
    const float* __restrict__ P2, const float* __restrict__ pb2,
    const float* __restrict__ A1, const float* __restrict__ ab1,
    const float* __restrict__ bn2_g, const float* __restrict__ bn2_b,
    const float* __restrict__ bn2_m, const float* __restrict__ bn2_v,
    const float* __restrict__ A2, const float* __restrict__ ab2)
{
    extern __shared__ char sm[];
    const int t = threadIdx.x;
    const uint32 smb = smem_u32(sm);

    float* s_key  = (float*)(sm + OFF_KEY);
    float* s_p1p  = (float*)(sm + OFF_P1P);
    float* s_wq   = (float*)(sm + OFF_WQ);
    float* s_b1p  = (float*)(sm + OFF_B1P);
    float* s_pb1p = (float*)(sm + OFF_PB1P);
    float* s_pb2  = (float*)(sm + OFF_PB2S);
    float* s_bqs  = (float*)(sm + OFF_BQS);
    float* s_s1   = (float*)(sm + OFF_S1S);
    float* s_s2   = (float*)(sm + OFF_S2S);
    float* s_posr = (float*)(sm + OFF_POSR);
    float* s_qy   = (float*)(sm + OFF_QY);
    float* s_vals = (float*)(sm + OFF_VALS);

    {
        float s2 = bn2_g[t] * rsqrtf(bn2_v[t] + 1e-5f);
        s_s2[t] = s2;
        s_b1p[t] = (ab1[t] - bn2_m[t]) * s2 + bn2_b[t];
    }
    if (t < 64) {
        float s1 = bn1_g[t] * rsqrtf(bn1_v[t] + 1e-5f);
        s_s1[t] = s1;
        s_pb1p[t] = (pb1[t] - bn1_m[t]) * s1 + bn1_b[t];
        s_pb2[t] = pb2[t];
        s_bqs[t] = bq_g[t];
    }
    if (t < 192) s_wq[t] = Wq_g[t];
    __syncthreads();
    if (t < 192) s_p1p[t] = P1[t] * s_s1[t / 3];
#pragma unroll
    for (int i = 0; i < 64; i++) {
        int idx = t + i * 256; int a = idx >> 6, c = idx & 63;
        *(__nv_bfloat16*)(sm + OFF_A1 + a * 128 + ((c * 2) ^ ((a & 7) << 4))) =
            __float2bfloat16(A1[idx] * s_s2[a]);
    }
#pragma unroll
    for (int i = 0; i < 64; i++) {
        int idx = t + i * 256; int c = idx >> 8, h = idx & 255;
        *(__nv_bfloat16*)(sm + OFF_A2 + c * 512 + ((h * 2) ^ ((c & 7) << 4))) =
            __float2bfloat16(A2[idx]);
    }
#pragma unroll
    for (int i = 0; i < 16; i++) {
        int idx = t + i * 256; int c = idx >> 6, h = idx & 63;
        *(__nv_bfloat16*)(sm + OFF_P2B + c * 128 + ((h * 2) ^ ((c & 7) << 4))) =
            __float2bfloat16(P2[idx]);
    }
    __syncthreads();

    const int lane = t & 31, w = t >> 5;
    const int g = lane >> 2, tig = lane & 3;
    const int e0 = w * 16;
    const int ar = lane & 15;
    const int acb = (lane >> 4) << 3;
    const int br = (lane & 7) + ((lane >> 4) << 3);
    const int bkb = (lane & 8) ? 8 : 0;
    const uint32 swsA = (uint32)((lane & 7) << 4);
    const uint32 aU_base  = smb + OFF_U   + (uint32)(e0 + ar) * 128;
    const uint32 aTH_base = smb + OFF_THB + (uint32)(e0 + ar) * 128;
    const uint32 aH_base  = smb + OFF_H1  + (uint32)(e0 + ar) * 512;
    const uint32 bA1_base = smb + OFF_A1  + (uint32)br * 128;
    const uint32 bA2_base = smb + OFF_A2  + (uint32)br * 512;
    const uint32 bP2_base = smb + OFF_P2B + (uint32)br * 128;

    for (int tile = blockIdx.x; tile < NTILES; tile += gridDim.x) {
        int b = tile >> 9;
        int n0 = (tile & 511) * 8;
        const float* xb = x + (size_t)b * 3 * NN;
        const int* idxb = &g_idx[(size_t)b * NN * KK];

        {
            int e = t & 127, cq = t >> 7;
            int pt = e >> 4, k = e & 15;
            int j = idxb[(n0 + pt) * KK + k];
            const float4* kp = (const float4*)&g_key_t[((size_t)b * NN + j) * CC + cq * 32];
            float* kd = &s_key[e * 68 + cq * 32];
#pragma unroll
            for (int q = 0; q < 8; q++) *(float4*)&kd[q * 4] = kp[q];
        }
        if (t < 128) {
            int pt = t >> 4, k = t & 15;
            int j = idxb[(n0 + pt) * KK + k];
#pragma unroll
            for (int d = 0; d < 3; d++)
                s_posr[(pt * 3 + d) * 16 + k] = xb[d * NN + n0 + pt] - xb[d * NN + j];
        }
        {
            int c6 = t & 63;
#pragma unroll
            for (int ss = 0; ss < 2; ss++) {
                int pt = (t >> 6) + ss * 4;
                int n = n0 + pt;
                s_qy[pt * 64 + c6] = s_bqs[c6] + s_wq[c6 * 3] * xb[n]
                    + s_wq[c6 * 3 + 1] * xb[NN + n] + s_wq[c6 * 3 + 2] * xb[2 * NN + n];
                s_vals[pt * 64 + c6] = g_val_t[((size_t)b * NN + n) * CC + c6];
            }
        }
        __syncthreads();

        {
            int e = t >> 1, h0 = (t & 1) * 32;
            int pt = e >> 4, k = e & 15;
            const float* pr = &s_posr[pt * 48];
            float px = pr[k], py = pr[16 + k], pz = pr[32 + k];
            uint32 sw = (uint32)((e & 7) << 4);
#pragma unroll
            for (int q = 0; q < 4; q++) {
                uint32 pk[4];
#pragma unroll
                for (int ii = 0; ii < 4; ii++) {
                    int h = h0 + q * 8 + ii * 2;
                    float f0 = fmaxf(s_pb1p[h] + s_p1p[h * 3] * px
                            + s_p1p[h * 3 + 1] * py + s_p1p[h * 3 + 2] * pz, 0.0f);
                    float f1 = fmaxf(s_pb1p[h + 1] + s_p1p[h * 3 + 3] * px
                            + s_p1p[h * 3 + 4] * py + s_p1p[h * 3 + 5] * pz, 0.0f);
                    CVTBF2(pk[ii], f0, f1);
                }
                *(uint4*)(sm + OFF_THB + e * 128 + (((uint32)((h0 + q * 8) * 2)) ^ sw)) = *(uint4*)pk;
            }
        }
        __syncwarp();

        float PE[8][4];
#pragma unroll
        for (int nt = 0; nt < 8; nt++)
#pragma unroll
            for (int q = 0; q < 4; q++) PE[nt][q] = 0.0f;
#pragma unroll
        for (int kk = 0; kk < 4; kk++) {
            uint32 A0, A1r, A2r, A3;
            ldsm4(A0, A1r, A2r, A3, aTH_base + (((uint32)((kk * 16 + acb) * 2)) ^ swsA));
#pragma unroll
            for (int ntp = 0; ntp < 4; ntp++) {
                uint32 b0, b1, b2, b3;
                ldsm4(b0, b1, b2, b3,
                      bP2_base + (uint32)((ntp * 16) * 128)
                               + (((uint32)((kk * 16 + bkb) * 2)) ^ swsA));
                mma16816(PE[ntp * 2][0], PE[ntp * 2][1], PE[ntp * 2][2], PE[ntp * 2][3],
                         A0, A1r, A2r, A3, b0, b1);
                mma16816(PE[ntp * 2 + 1][0], PE[ntp * 2 + 1][1], PE[ntp * 2 + 1][2], PE[ntp * 2 + 1][3],
                         A0, A1r, A2r, A3, b2, b3);
            }
        }
        {
            int row0 = e0 + g, row1 = e0 + 8 + g;
#pragma unroll
            for (int nt = 0; nt < 8; nt++) {
                int c0 = nt * 8 + 2 * tig;
                float pb0 = s_pb2[c0], pb1v = s_pb2[c0 + 1];
                PE[nt][0] += pb0; PE[nt][1] += pb1v;
                PE[nt][2] += pb0; PE[nt][3] += pb1v;
                float2 qv = *(const float2*)&s_qy[w * 64 + c0];
                float2 kA = *(const float2*)&s_key[row0 * 68 + c0];
                float2 kB = *(const float2*)&s_key[row1 * 68 + c0];
                float u00 = (qv.x - kA.x) + PE[nt][0];
                float u01 = (qv.y - kA.y) + PE[nt][1];
                float u10 = (qv.x - kB.x) + PE[nt][2];
                float u11 = (qv.y - kB.y) + PE[nt][3];
                uint32 p0, p1;
                CVTBF2(p0, u00, u01);
                CVTBF2(p1, u10, u11);
                uint32 co = ((uint32)(c0 * 2)) ^ ((uint32)(g << 4));
                *(uint32*)(sm + OFF_U + row0 * 128 + co) = p0;
                *(uint32*)(sm + OFF_U + row1 * 128 + co) = p1;
            }
        }
        __syncwarp();

        uint32 AU[4][4];
#pragma unroll
        for (int kk = 0; kk < 4; kk++)
            ldsm4(AU[kk][0], AU[kk][1], AU[kk][2], AU[kk][3],
                  aU_base + (((uint32)((kk * 16 + acb) * 2)) ^ swsA));
        __syncthreads();

#pragma unroll
        for (int chunk = 0; chunk < 4; chunk++) {
            float acc[8][4];
#pragma unroll
            for (int nt = 0; nt < 8; nt++)
#pragma unroll
                for (int q = 0; q < 4; q++) acc[nt][q] = 0.0f;
#pragma unroll
            for (int kk = 0; kk < 4; kk++) {
#pragma unroll
                for (int ntp = 0; ntp < 4; ntp++) {
                    uint32 b0, b1, b2, b3;
                    ldsm4(b0, b1, b2, b3,
                          bA1_base + (uint32)((chunk * 64 + ntp * 16) * 128)
                                   + (((uint32)((kk * 16 + bkb) * 2)) ^ swsA));
                    mma16816(acc[ntp * 2][0], acc[ntp * 2][1], acc[ntp * 2][2], acc[ntp * 2][3],
                             AU[kk][0], AU[kk][1], AU[kk][2], AU[kk][3], b0, b1);
                    mma16816(acc[ntp * 2 + 1][0], acc[ntp * 2 + 1][1], acc[ntp * 2 + 1][2], acc[ntp * 2 + 1][3],
                             AU[kk][0], AU[kk][1], AU[kk][2], AU[kk][3], b2, b3);
                }
            }
            int row0 = e0 + g, row1 = e0 + 8 + g;
            uint32 swg = (uint32)(g << 4);
#pragma unroll
            for (int nt = 0; nt < 8; nt++) {
                int a0 = chunk * 64 + nt * 8 + 2 * tig;
                float b0v = s_b1p[a0], b1v = s_b1p[a0 + 1];
                float h00 = fmaxf(acc[nt][0] + b0v, 0.0f);
                float h01 = fmaxf(acc[nt][1] + b1v, 0.0f);
                float h10 = fmaxf(acc[nt][2] + b0v, 0.0f);
                float h11 = fmaxf(acc[nt][3] + b1v, 0.0f);
                uint32 p0, p1;
                CVTBF2(p0, h00, h01);
                CVTBF2(p1, h10, h11);
                uint32 co = ((uint32)(a0 * 2)) ^ swg;
                *(uint32*)(sm + OFF_H1 + row0 * 512 + co) = p0;
                *(uint32*)(sm + OFF_H1 + row1 * 512 + co) = p1;
            }
        }
        __syncwarp();

        float ac2[8][4];
#pragma unroll
        for (int nt = 0; nt < 8; nt++)
#pragma unroll
            for (int q = 0; q < 4; q++) ac2[nt][q] = 0.0f;
#pragma unroll 4
        for (int kk = 0; kk < 16; kk++) {
            uint32 A0, A1r, A2r, A3;
            ldsm4(A0, A1r, A2r, A3, aH_base + (((uint32)((kk * 16 + acb) * 2)) ^ swsA));
#pragma unroll
            for (int ntp = 0; ntp < 4; ntp++) {
                uint32 b0, b1, b2, b3;
                ldsm4(b0, b1, b2, b3,
                      bA2_base + (uint32)((ntp * 16) * 512)
                               + (((uint32)((kk * 16 + bkb) * 2)) ^ swsA));
                mma16816(ac2[ntp * 2][0], ac2[ntp * 2][1], ac2[ntp * 2][2], ac2[ntp * 2][3],
                         A0, A1r, A2r, A3, b0, b1);
                mma16816(ac2[ntp * 2 + 1][0], ac2[ntp * 2 + 1][1], ac2[ntp * 2 + 1][2], ac2[ntp * 2 + 1][3],
                         A0, A1r, A2r, A3, b2, b3);
            }
        }

        {
            size_t orow = ((size_t)b * NN + n0 + w) * CC;
#pragma unroll
            for (int nt = 0; nt < 8; nt++) {
                int c0 = nt * 8 + 2 * tig;
                float ex0 = __expf(ac2[nt][0]);
                float ex1 = __expf(ac2[nt][1]);
                float ex2 = __expf(ac2[nt][2]);
                float ex3 = __expf(ac2[nt][3]);
                float sv0 = ex0 + ex2, sv1 = ex1 + ex3;
                float tv0 = ex0 * PE[nt][0] + ex2 * PE[nt][2];
                float tv1 = ex1 * PE[nt][1] + ex3 * PE[nt][3];
                sv0 += __shfl_xor_sync(0xFFFFFFFFu, sv0, 4);
                sv1 += __shfl_xor_sync(0xFFFFFFFFu, sv1, 4);
                tv0 += __shfl_xor_sync(0xFFFFFFFFu, tv0, 4);
                tv1 += __shfl_xor_sync(0xFFFFFFFFu, tv1, 4);
                sv0 += __shfl_xor_sync(0xFFFFFFFFu, sv0, 8);
                sv1 += __shfl_xor_sync(0xFFFFFFFFu, sv1, 8);
                tv0 += __shfl_xor_sync(0xFFFFFFFFu, tv0, 8);
                tv1 += __shfl_xor_sync(0xFFFFFFFFu, tv1, 8);
                sv0 += __shfl_xor_sync(0xFFFFFFFFu, sv0, 16);
                sv1 += __shfl_xor_sync(0xFFFFFFFFu, sv1, 16);
                tv0 += __shfl_xor_sync(0xFFFFFFFFu, tv0, 16);
                tv1 += __shfl_xor_sync(0xFFFFFFFFu, tv1, 16);
                if (lane < 4) {
                    g_agg[orow + c0]     = s_vals[w * 64 + c0] + __fdividef(tv0, sv0);
                    g_agg[orow + c0 + 1] = s_vals[w * 64 + c0 + 1] + __fdividef(tv1, sv1);
                }
            }
        }
        __syncthreads();
    }
}

// ================= Kernel 4: out = W_end @ agg + b_end + y =================
__global__ __launch_bounds__(256) void k_end(
    const float* __restrict__ y, const float* __restrict__ We_g,
    const float* __restrict__ be_g, float* __restrict__ out)
{
    __shared__ float As[64][65];
    __shared__ float Ws[64][64];
    int b = blockIdx.y, n0 = blockIdx.x * 64, t = threadIdx.x;
#pragma unroll
    for (int i = 0; i < 16; i++) { int e = t + i * 256; Ws[e >> 6][e & 63] = We_g[e]; }
#pragma unroll
    for (int i = 0; i < 16; i++) {
        int e = t + i * 256; int p = e >> 6, c = e & 63;
        As[p][c] = g_agg[((size_t)b * NN + n0 + p) * CC + c];
    }
    __syncthreads();
    int p = t & 63, og = t >> 6;
    float acc[16];
#pragma unroll
    for (int i = 0; i < 16; i++) acc[i] = be_g[og * 16 + i];
#pragma unroll 4
    for (int c = 0; c < 64; c++) {
        float av = As[p][c];
#pragma unroll
        for (int i = 0; i < 16; i++) acc[i] = fmaf(Ws[og * 16 + i][c], av, acc[i]);
    }
#pragma unroll
    for (int i = 0; i < 16; i++) {
        int o = og * 16 + i;
        size_t off = ((size_t)b * CC + o) * NN + n0 + p;
        out[off] = acc[i] + y[off];
    }
}

// ================= launcher (k_knn_part is 4th launch -> profiled) =================
extern "C" void kernel_launch(void* const* d_in, const int* in_sizes, int n_in,
                              void* d_out, int out_size)
{
    const float* x       = (const float*)d_in[0];
    const float* y       = (const float*)d_in[1];
    const float* W_start = (const float*)d_in[2];
    const float* b_start = (const float*)d_in[3];
    const float* W_key   = (const float*)d_in[4];
    const float* b_key   = (const float*)d_in[5];
    const float* W_query = (const float*)d_in[6];
    const float* b_query = (const float*)d_in[7];
    const float* P1      = (const float*)d_in[8];
    const float* pb1     = (const float*)d_in[9];
    const float* bn1_g   = (const float*)d_in[10];
    const float* bn1_b   = (const float*)d_in[11];
    const float* bn1_m   = (const float*)d_in[12];
    const float* bn1_v   = (const float*)d_in[13];
    const float* P2      = (const float*)d_in[14];
    const float* pb2     = (const float*)d_in[15];
    const float* A1      = (const float*)d_in[16];
    const float* ab1     = (const float*)d_in[17];
    const float* bn2_g   = (const float*)d_in[18];
    const float* bn2_b   = (const float*)d_in[19];
    const float* bn2_m   = (const float*)d_in[20];
    const float* bn2_v   = (const float*)d_in[21];
    const float* A2      = (const float*)d_in[22];
    const float* ab2     = (const float*)d_in[23];
    const float* W_end   = (const float*)d_in[24];
    const float* b_end   = (const float*)d_in[25];

    cudaFuncSetAttribute(k_attn, cudaFuncAttributeMaxDynamicSharedMemorySize, SM_TOTAL);

    k_dummy<<<1, 32>>>();                                                                // 1
    k_linear_start_key<<<dim3(NN / 64, BB), 256>>>(y, W_start, b_start, W_key, b_key);   // 2
    k_dummy2<<<1, 32>>>();                                                               // 3
    k_knn_part<<<dim3(NN / 128, NSPL, BB), 128>>>(x);                                    // 4 <- profiled
    k_knn_merge<<<BB * NN / 128, 128>>>();                                               // 5
    k_attn<<<148, 256, SM_TOTAL>>>(x, W_query, b_query,
                                   P1, pb1, bn1_g, bn1_b, bn1_m, bn1_v,
                                   P2, pb2, A1, ab1,
                                   bn2_g, bn2_b, bn2_m, bn2_v, A2, ab2);                 // 6
    k_end<<<dim3(NN / 64, BB), 256>>>(y, W_end, b_end, (float*)d_out);                   // 7
}